// round 13
// baseline (speedup 1.0000x reference)
#include <cuda_runtime.h>
#include <cuda_bf16.h>
#include <math.h>
#include <stdint.h>

#define NND 2048
#define NNE (NND*NND)

// ---------------- device scratch ----------------
__device__ float g_A0[4u*NNE];
__device__ float g_Wh[4*NND*64];
__device__ unsigned short g_WhTh[4*64*NND], g_WhTl[4*64*NND];
__device__ float g_s1[4*NND], g_s2[4*NND];
__device__ float g_Whout[NND*16];
__device__ float g_s1o[NND], g_s2o[NND];
__device__ float g_hpA[NND*1024], g_hpB[NND*1024];
__device__ float g_u0[4*NND], g_w0[4*NND], g_il0[4];
__device__ float g_uh[16*NND], g_wh2[16*NND], g_ilh[16];
__device__ float g_uo[4*NND], g_wo[4*NND], g_ilo[4];
__device__ float g_mean[16], g_rstd[16];

#define OFF_RC0 0
#define OFF_RR0 (4*NND)
#define OFF_HC  (8*NND)
#define OFF_HR  (24*NND)
#define OFF_OC  (40*NND)
#define OFF_OR  (44*NND)
#define OFF_GS  (48*NND)
#define OFF_X2  (48*NND+256)
#define SMALL_TOTAL (48*NND+256+NND*16)
__device__ float g_small[SMALL_TOTAL];

__device__ __forceinline__ float wred(float v){
    v += __shfl_down_sync(0xffffffffu, v, 16);
    v += __shfl_down_sync(0xffffffffu, v, 8);
    v += __shfl_down_sync(0xffffffffu, v, 4);
    v += __shfl_down_sync(0xffffffffu, v, 2);
    v += __shfl_down_sync(0xffffffffu, v, 1);
    return v;
}
__device__ __forceinline__ float leaky(float x){ return x > 0.f ? x : 0.2f*x; }
__device__ __forceinline__ float elu1(float x){ return x > 0.f ? x : (expf(x)-1.f); }
__device__ __forceinline__ unsigned short bfh(float x){ return __bfloat16_as_ushort(__float2bfloat16(x)); }
__device__ __forceinline__ float bff(unsigned short u){ return __bfloat162float(__ushort_as_bfloat16(u)); }
// packed: result = {hi16=cvt(a), lo16=cvt(b)}
__device__ __forceinline__ uint32_t cvt2(float a, float b){
    uint32_t r; asm("cvt.rn.bf16x2.f32 %0, %1, %2;" : "=r"(r) : "f"(a), "f"(b)); return r;
}

__device__ __forceinline__ uint32_t smem_u32(const void* p){
    uint32_t a; asm("{ .reg .u64 t; cvta.to.shared.u64 t, %1; cvt.u32.u64 %0, t; }" : "=r"(a) : "l"(p)); return a;
}
__device__ __forceinline__ void ldmx4(uint32_t* r, uint32_t addr){
    asm volatile("ldmatrix.sync.aligned.m8n8.x4.shared.b16 {%0,%1,%2,%3},[%4];"
        : "=r"(r[0]),"=r"(r[1]),"=r"(r[2]),"=r"(r[3]) : "r"(addr));
}
__device__ __forceinline__ void mmabf(float* d, const uint32_t* a, const uint32_t* b){
    asm volatile("mma.sync.aligned.m16n8k16.row.col.f32.bf16.bf16.f32 "
        "{%0,%1,%2,%3},{%4,%5,%6,%7},{%8,%9},{%0,%1,%2,%3};"
        : "+f"(d[0]),"+f"(d[1]),"+f"(d[2]),"+f"(d[3])
        : "r"(a[0]),"r"(a[1]),"r"(a[2]),"r"(a[3]),"r"(b[0]),"r"(b[1]));
}

// smem layout for headmm (bytes). att row stride 80B (32 bf16 + 8 pad).
#define OF_AH 0
#define OF_AL 40960
#define OF_B  81920
#define OF_W  122880
#define OF_S2 124928
#define OF_U  125440
#define OF_IL 127488
#define OF_TOT 127552

// ---------------- zero ----------------
__global__ void k_zero(){
    int i = blockIdx.x*256 + threadIdx.x;
    if(i < SMALL_TOTAL) g_small[i] = 0.f;
}

// ---------------- Wh = X @ W_heads[h] (+ fused s1/s2) ----------------
__global__ void k_wh(const float* __restrict__ X, const float* __restrict__ W,
                     const float* __restrict__ ah){
    int h = blockIdx.y;
    int nb = blockIdx.x*4;
    int t = threadIdx.x;
    __shared__ float Xs[4][128];
    __shared__ float aS[4][64];
    #pragma unroll
    for(int q=0;q<2;q++){
        int idx = t + q*256;
        Xs[idx>>7][idx&127] = X[(size_t)(nb + (idx>>7))*128 + (idx&127)];
    }
    __syncthreads();
    int nl = t>>6, f = t&63;
    float a = 0.f;
    #pragma unroll 16
    for(int k=0;k<128;k++)
        a = fmaf(Xs[nl][k], W[((size_t)h*128 + k)*64 + f], a);
    g_Wh[((size_t)h*NND + nb + nl)*64 + f] = a;
    aS[nl][f] = a;
    __syncthreads();
    int w = t>>5, l = t&31;
    if(w < 4){
        float v0 = aS[w][l], v1 = aS[w][l+32];
        float s1 = fmaf(v0, ah[h*128 + l],      v1*ah[h*128 + l + 32]);
        float s2 = fmaf(v0, ah[h*128 + 64 + l], v1*ah[h*128 + 96 + l]);
        s1 = wred(s1); s2 = wred(s2);
        if(l == 0){
            g_s1[h*NND + nb + w] = s1;
            g_s2[h*NND + nb + w] = s2;
        }
    }
}

// ---------------- WhT hi/lo split (smem transpose, coalesced both ways) ----------------
__global__ void k_whsplit(){
    int h = blockIdx.y;
    int m0 = blockIdx.x*32;
    __shared__ float tile[32][65];
    int t = threadIdx.x;
    #pragma unroll
    for(int q=0;q<8;q++){
        int idx = t + q*256;
        tile[idx>>6][idx&63] = g_Wh[((size_t)h*NND + m0 + (idx>>6))*64 + (idx&63)];
    }
    __syncthreads();
    #pragma unroll
    for(int q=0;q<8;q++){
        int idx = t + q*256;
        int f = idx>>5, m = idx&31;
        float v = tile[m][f];
        unsigned short hi = bfh(v);
        g_WhTh[(size_t)(h*64+f)*NND + m0 + m] = hi;
        g_WhTl[(size_t)(h*64+f)*NND + m0 + m] = bfh(v - bff(hi));
    }
}

// ---------------- raw ef sums: rows + cols fused ----------------
__global__ void k_rawA(const float4* __restrict__ ef){
    __shared__ float rp[4][8][9];
    int t = threadIdx.x, w = t>>5;
    int i0 = blockIdx.x*8;
    float colacc[8][4];
    #pragma unroll
    for(int jb=0;jb<8;jb++)
        #pragma unroll
        for(int c=0;c<4;c++) colacc[jb][c] = 0.f;
    for(int ii=0; ii<8; ii++){
        int i = i0 + ii;
        float a0=0.f,a1=0.f,a2=0.f,a3=0.f;
        #pragma unroll
        for(int jb=0;jb<8;jb++){
            float4 v = ef[(size_t)i*NND + jb*256 + t];
            a0+=v.x; a1+=v.y; a2+=v.z; a3+=v.w;
            colacc[jb][0]+=v.x; colacc[jb][1]+=v.y; colacc[jb][2]+=v.z; colacc[jb][3]+=v.w;
        }
        float r0=wred(a0), r1=wred(a1), r2=wred(a2), r3=wred(a3);
        if((t&31)==0){ rp[0][ii][w]=r0; rp[1][ii][w]=r1; rp[2][ii][w]=r2; rp[3][ii][w]=r3; }
    }
    __syncthreads();
    if(t < 32){
        int c = t>>3, ii = t&7;
        float s = 0.f;
        for(int q=0;q<8;q++) s += rp[c][ii][q];
        g_small[OFF_RR0 + c*NND + i0 + ii] = s;
    }
    #pragma unroll
    for(int jb=0;jb<8;jb++){
        int j = jb*256 + t;
        atomicAdd(&g_small[OFF_RC0 + 0*NND + j], colacc[jb][0]);
        atomicAdd(&g_small[OFF_RC0 + 1*NND + j], colacc[jb][1]);
        atomicAdd(&g_small[OFF_RC0 + 2*NND + j], colacc[jb][2]);
        atomicAdd(&g_small[OFF_RC0 + 3*NND + j], colacc[jb][3]);
    }
}

// ---------------- dsn params ----------------
__global__ void k_params(int mode){
    int ch = blockIdx.x, t = threadIdx.x;
    const float *rs, *cs; float *u, *w, *il;
    if(mode==0){ rs=g_small+OFF_RR0+ch*NND; cs=g_small+OFF_RC0+ch*NND; u=g_u0+ch*NND; w=g_w0+ch*NND; il=g_il0+ch; }
    else if(mode==1){ rs=g_small+OFF_HR+ch*NND; cs=g_small+OFF_HC+ch*NND; u=g_uh+ch*NND; w=g_wh2+ch*NND; il=g_ilh+ch; }
    else { rs=g_small+OFF_OR+ch*NND; cs=g_small+OFF_OC+ch*NND; u=g_uo+ch*NND; w=g_wo+ch*NND; il=g_ilo+ch; }
    __shared__ float smx[256], ssm[256];
    __shared__ float lamS, irS, ilS;
    float mx = -3.4e38f, sm = 0.f;
    #pragma unroll
    for(int q=0;q<8;q++){
        float a = rs[t + q*256]; mx = fmaxf(mx, a); sm += a;
        float b = cs[t + q*256]; mx = fmaxf(mx, b);
    }
    smx[t] = mx; ssm[t] = sm;
    __syncthreads();
    for(int s=128; s; s>>=1){
        if(t < s){ smx[t] = fmaxf(smx[t], smx[t+s]); ssm[t] += ssm[t+s]; }
        __syncthreads();
    }
    if(t==0){
        float lam = smx[0];
        float r = (float)NND*lam - ssm[0];
        lamS = lam; irS = 1.f/r; ilS = 1.f/lam;
        il[0] = ilS;
    }
    __syncthreads();
    float lam = lamS, ir = irS, ilv = ilS;
    #pragma unroll
    for(int q=0;q<8;q++){
        int i = t + q*256;
        u[i] = (lam - rs[i]) * ir;
        w[i] = (lam - cs[i]) * ilv;
    }
}

// ---------------- build A0 + head row sums (warp-per-row) ----------------
__global__ void k_headA(const float4* __restrict__ ef){
    int t = threadIdx.x, w = t>>5, l = t&31;
    int i = blockIdx.x*8 + w;
    float il0v[4], s1v[4], u0v[4];
    #pragma unroll
    for(int c=0;c<4;c++) il0v[c] = g_il0[c];
    #pragma unroll
    for(int h=0;h<4;h++) s1v[h] = g_s1[h*NND + i];
    #pragma unroll
    for(int c=0;c<4;c++) u0v[c] = g_u0[c*NND + i];
    float acc[16];
    #pragma unroll
    for(int k=0;k<16;k++) acc[k] = 0.f;
    #pragma unroll 4
    for(int jb=0; jb<64; jb++){
        int j = jb*32 + l;
        float4 tv = ef[(size_t)i*NND + j];
        float tt[4] = {tv.x, tv.y, tv.z, tv.w};
        float A[4];
        #pragma unroll
        for(int c=0;c<4;c++){
            float w0 = g_w0[c*NND + j];
            A[c] = tt[c] > 0.f ? fmaf(tt[c], il0v[c], u0v[c]*w0) : tt[c];
        }
        ((float4*)g_A0)[(size_t)i*NND + j] = make_float4(A[0],A[1],A[2],A[3]);
        float P = 1.f;
        #pragma unroll
        for(int h=0;h<4;h++){
            P *= leaky(s1v[h] + g_s2[h*NND + j]);
            #pragma unroll
            for(int c=0;c<4;c++) acc[h*4+c] += A[c]*P;
        }
    }
    #pragma unroll
    for(int k=0;k<16;k++){
        float r = wred(acc[k]);
        if(l == 0) g_small[OFF_HR + k*NND + i] = r;
    }
}

// ---------------- head col sums ----------------
__global__ void k_headB(){
    __shared__ float cs[8][16][33];
    int t = threadIdx.x;
    int jl = t&31, ig = t>>5;
    int j = blockIdx.x*32 + jl;
    int ibase = blockIdx.y*512 + ig*64;
    float s2v[4];
    #pragma unroll
    for(int h=0;h<4;h++) s2v[h] = g_s2[h*NND + j];
    float acc[16];
    #pragma unroll
    for(int k=0;k<16;k++) acc[k] = 0.f;
    const float4* a4 = (const float4*)g_A0;
    for(int r=0;r<64;r++){
        int i = ibase + r;
        float4 Av = a4[(size_t)i*NND + j];
        float A[4] = {Av.x, Av.y, Av.z, Av.w};
        float P = 1.f;
        #pragma unroll
        for(int h=0;h<4;h++){
            P *= leaky(g_s1[h*NND + i] + s2v[h]);
            #pragma unroll
            for(int c=0;c<4;c++) acc[h*4+c] += A[c]*P;
        }
    }
    #pragma unroll
    for(int k=0;k<16;k++) cs[ig][k][jl] = acc[k];
    __syncthreads();
    #pragma unroll
    for(int q=0;q<2;q++){
        int idx = t + q*256;
        int k = idx>>5, jj = idx&31;
        float s = 0.f;
        for(int g=0;g<8;g++) s += cs[g][k][jj];
        atomicAdd(&g_small[OFF_HC + k*NND + blockIdx.x*32 + jj], s);
    }
}

// ---------------- attention @ Wh, all 4 heads per A0 read ----------------
__global__ void __launch_bounds__(512,1) k_headmm_mma(){
    extern __shared__ char sm[];
    int t = threadIdx.x;
    int n0g = blockIdx.x*32;
    int khalf = blockIdx.y;
    uint32_t sb = smem_u32(sm);

    float* wS  = (float*)(sm + OF_W);
    float* s2S = (float*)(sm + OF_S2);
    float* uS  = (float*)(sm + OF_U);
    float* ilS = (float*)(sm + OF_IL);

    if(t < 512){
        int combo = t>>5, n = t&31;
        uS[combo*32 + n] = g_uh[combo*NND + n0g + n];
    }
    if(t < 16) ilS[t] = g_ilh[t];

    int bn = t>>4;
    int bm = (t&15)*2;
    float s1v[4];
    #pragma unroll
    for(int mh=0; mh<4; mh++) s1v[mh] = g_s1[mh*NND + n0g + bn];

    float acc[2][8][4];
    #pragma unroll
    for(int a=0;a<2;a++)
        #pragma unroll
        for(int b=0;b<8;b++)
            #pragma unroll
            for(int q=0;q<4;q++) acc[a][b][q] = 0.f;

    int wI = t>>5, l = t&31;
    int wh = wI>>2, wc = wI&3;
    int lr = l&15, lc = l>>4;
    uint32_t aBaseH = sb + OF_AH + wI*2560;
    uint32_t aBaseL = sb + OF_AL + wI*2560;
    uint32_t bBaseH = sb + OF_B + (wh*2+0)*5120;
    uint32_t bBaseL = sb + OF_B + (wh*2+1)*5120;
    uint32_t bf = (uint32_t)((l&7) + ((l>>4)<<3));

    for(int ck=0; ck<32; ck++){
        int m0 = khalf*1024 + ck*32;
        __syncthreads();
        wS[t&511] = g_wh2[(t>>5)*NND + m0 + (t&31)];
        if(t < 128) s2S[t] = g_s2[(t>>5)*NND + m0 + (t&31)];
        if(t < 256){
            int h = t>>6, f = t&63;
            const uint4* ph = (const uint4*)&g_WhTh[(size_t)(h*64+f)*NND + m0];
            const uint4* pl = (const uint4*)&g_WhTl[(size_t)(h*64+f)*NND + m0];
            uint4* dh = (uint4*)(sm + OF_B + (h*2+0)*5120 + f*80);
            uint4* dl = (uint4*)(sm + OF_B + (h*2+1)*5120 + f*80);
            dh[0]=ph[0]; dh[1]=ph[1]; dh[2]=ph[2]; dh[3]=ph[3];
            dl[0]=pl[0]; dl[1]=pl[1]; dl[2]=pl[2]; dl[3]=pl[3];
        }
        __syncthreads();
        {
            const float4* ap = (const float4*)g_A0 + (size_t)(n0g+bn)*NND + m0 + bm;
            float4 Aa = ap[0], Ab = ap[1];
            float Aav[4] = {Aa.x, Aa.y, Aa.z, Aa.w};
            float Abv[4] = {Ab.x, Ab.y, Ab.z, Ab.w};
            float Pa = 1.f, Pb = 1.f;
            float Pah[4], Pbh[4];
            #pragma unroll
            for(int mh=0; mh<4; mh++){
                Pa *= leaky(s1v[mh] + s2S[mh*32 + bm]);
                Pb *= leaky(s1v[mh] + s2S[mh*32 + bm + 1]);
                Pah[mh] = Pa; Pbh[mh] = Pb;
            }
            uint32_t off = (uint32_t)(bn*80 + bm*2);
            #pragma unroll
            for(int combo=0; combo<16; combo++){
                int h = combo>>2, c = combo&3;
                float il = ilS[combo];
                float uvv = uS[combo*32 + bn];
                float wa = wS[combo*32 + bm], wb = wS[combo*32 + bm + 1];
                float ea = Aav[c]*Pah[h], eb = Abv[c]*Pbh[h];
                float xa = ea > 0.f ? fmaf(ea, il, uvv*wa) : ea;
                float xb = eb > 0.f ? fmaf(eb, il, uvv*wb) : eb;
                uint32_t hw = cvt2(xb, xa);
                float haf = __uint_as_float(hw << 16);
                float hbf = __uint_as_float(hw & 0xFFFF0000u);
                uint32_t lw = cvt2(xb - hbf, xa - haf);
                *(uint32_t*)(sm + OF_AH + combo*2560 + off) = hw;
                *(uint32_t*)(sm + OF_AL + combo*2560 + off) = lw;
            }
        }
        __syncthreads();
        #pragma unroll
        for(int ki=0; ki<2; ki++){
            uint32_t aH[2][4], aL[2][4];
            #pragma unroll
            for(int mi=0; mi<2; mi++){
                uint32_t ro = (uint32_t)((mi*16 + lr)*80 + (ki*16 + lc*8)*2);
                ldmx4(aH[mi], aBaseH + ro);
                ldmx4(aL[mi], aBaseL + ro);
            }
            uint32_t bk = (uint32_t)(ki*16 + ((l>>3)&1)*8);
            #pragma unroll
            for(int np=0; np<4; np++){
                uint32_t bo = (np*16 + bf)*80 + bk*2;
                uint32_t bH[4], bL[4];
                ldmx4(bH, bBaseH + bo);
                ldmx4(bL, bBaseL + bo);
                #pragma unroll
                for(int mi=0; mi<2; mi++){
                    mmabf(acc[mi][np*2],   aH[mi], bH);
                    mmabf(acc[mi][np*2],   aL[mi], bH);
                    mmabf(acc[mi][np*2],   aH[mi], bL);
                    mmabf(acc[mi][np*2+1], aH[mi], bH+2);
                    mmabf(acc[mi][np*2+1], aL[mi], bH+2);
                    mmabf(acc[mi][np*2+1], aH[mi], bL+2);
                }
            }
        }
    }
    float* hpK = khalf == 0 ? g_hpA : g_hpB;
    #pragma unroll
    for(int mi=0; mi<2; mi++){
        int nr = n0g + mi*16 + (l>>2);
        #pragma unroll
        for(int ni=0; ni<8; ni++){
            int f = ni*8 + (l&3)*2;
            float* dst = &hpK[(size_t)nr*1024 + wh*256 + wc*64 + f];
            *(float2*)dst = make_float2(acc[mi][ni][0], acc[mi][ni][1]);
            *(float2*)(dst + 8*1024) = make_float2(acc[mi][ni][2], acc[mi][ni][3]);
        }
    }
}

// ---------------- Whout = elu(hpA+hpB) @ W_out ----------------
__global__ void k_whout(const float* __restrict__ Wout){
    int n = blockIdx.x;
    int t = threadIdx.x;
    __shared__ float eS[1024];
    __shared__ float part[16][17];
    {
        float4 ha = ((const float4*)(g_hpA + (size_t)n*1024))[t];
        float4 hb = ((const float4*)(g_hpB + (size_t)n*1024))[t];
        eS[t*4+0] = elu1(ha.x + hb.x);
        eS[t*4+1] = elu1(ha.y + hb.y);
        eS[t*4+2] = elu1(ha.z + hb.z);
        eS[t*4+3] = elu1(ha.w + hb.w);
    }
    __syncthreads();
    int g = t&15, kg = t>>4;
    float s = 0.f;
    #pragma unroll 8
    for(int k=0;k<64;k++)
        s = fmaf(eS[kg*64+k], Wout[(size_t)(kg*64+k)*16 + g], s);
    part[kg][g] = s;
    __syncthreads();
    if(t < 16){
        float a = 0.f;
        for(int q=0;q<16;q++) a += part[q][t];
        g_Whout[n*16 + t] = a;
    }
}

__global__ void k_s12o(const float* __restrict__ aout){
    int n = blockIdx.x*256 + threadIdx.x;
    float s1 = 0.f, s2 = 0.f;
    #pragma unroll
    for(int g=0;g<16;g++){
        float v = g_Whout[n*16+g];
        s1 = fmaf(v, aout[g],    s1);
        s2 = fmaf(v, aout[16+g], s2);
    }
    g_s1o[n] = s1; g_s2o[n] = s2;
}

// ---------------- out-layer e: write edge_attr + row/col sums fused ----------------
__global__ void k_outA(float* __restrict__ dout){
    __shared__ float rp[4][8][9];
    int t = threadIdx.x, w = t>>5;
    int i0 = blockIdx.x*8;
    float* eo = dout + 128;
    const float4* a4 = (const float4*)g_A0;
    float colacc[8][4];
    #pragma unroll
    for(int jb=0;jb<8;jb++)
        #pragma unroll
        for(int c=0;c<4;c++) colacc[jb][c] = 0.f;
    for(int ii=0; ii<8; ii++){
        int i = i0 + ii;
        float s1v[4];
        #pragma unroll
        for(int h=0;h<4;h++) s1v[h] = g_s1[h*NND + i];
        float s1ov = g_s1o[i];
        float a0=0.f,a1=0.f,a2=0.f,a3=0.f;
        #pragma unroll
        for(int jb=0;jb<8;jb++){
            int j = jb*256 + t;
            float4 Av = a4[(size_t)i*NND + j];
            float P = 1.f;
            #pragma unroll
            for(int h=0;h<4;h++) P *= leaky(s1v[h] + g_s2[h*NND + j]);
            P *= leaky(s1ov + g_s2o[j]);
            float e0 = Av.x*P, e1 = Av.y*P, e2 = Av.z*P, e3 = Av.w*P;
            eo[0u*NNE + (size_t)i*NND + j] = e0;
            eo[1u*NNE + (size_t)i*NND + j] = e1;
            eo[2u*NNE + (size_t)i*NND + j] = e2;
            eo[3u*NNE + (size_t)i*NND + j] = e3;
            a0 += e0; a1 += e1; a2 += e2; a3 += e3;
            colacc[jb][0]+=e0; colacc[jb][1]+=e1; colacc[jb][2]+=e2; colacc[jb][3]+=e3;
        }
        float r0=wred(a0), r1=wred(a1), r2=wred(a2), r3=wred(a3);
        if((t&31)==0){ rp[0][ii][w]=r0; rp[1][ii][w]=r1; rp[2][ii][w]=r2; rp[3][ii][w]=r3; }
    }
    __syncthreads();
    if(t < 32){
        int c = t>>3, ii = t&7;
        float s = 0.f;
        for(int q=0;q<8;q++) s += rp[c][ii][q];
        g_small[OFF_OR + c*NND + i0 + ii] = s;
    }
    #pragma unroll
    for(int jb=0;jb<8;jb++){
        int j = jb*256 + t;
        atomicAdd(&g_small[OFF_OC + 0*NND + j], colacc[jb][0]);
        atomicAdd(&g_small[OFF_OC + 1*NND + j], colacc[jb][1]);
        atomicAdd(&g_small[OFF_OC + 2*NND + j], colacc[jb][2]);
        atomicAdd(&g_small[OFF_OC + 3*NND + j], colacc[jb][3]);
    }
}

// ---------------- out-layer: x2 = sum_c dsn(eo_c) @ Whout (reads stored e) ----------------
__global__ void k_outmm(const float* __restrict__ dout){
    int n0 = blockIdx.x*32;
    int kbase = blockIdx.y*512;
    int t = threadIdx.x;
    __shared__ float asS[32][33];
    __shared__ float woS[32][16];
    __shared__ float uoS[4][32], iloS[4];
    const float* eo = dout + 128;
    if(t < 32){
        #pragma unroll
        for(int c=0;c<4;c++) uoS[c][t] = g_uo[c*NND + n0 + t];
    }
    if(t < 4) iloS[t] = g_ilo[t];
    int bn = t>>3, bm4 = (t&7)*4;
    int na = t>>3, gp = (t&7)*2;
    float acc0 = 0.f, acc1 = 0.f;
    __syncthreads();
    for(int mt=0; mt<16; mt++){
        int m0 = kbase + mt*32;
        ((float*)woS)[t]       = g_Whout[(size_t)m0*16 + t];
        ((float*)woS)[t+256]   = g_Whout[(size_t)m0*16 + t + 256];
        #pragma unroll
        for(int k=0;k<4;k++){
            int m = bm4 + k, mg = m0 + m;
            size_t base = (size_t)(n0+bn)*NND + mg;
            float s = 0.f;
            #pragma unroll
            for(int c=0;c<4;c++){
                float e = eo[(size_t)c*NNE + base];
                float wv = g_wo[c*NND + mg];
                s += e > 0.f ? fmaf(e, iloS[c], uoS[c][bn]*wv) : e;
            }
            asS[bn][m] = s;
        }
        __syncthreads();
        #pragma unroll 8
        for(int m=0;m<32;m++){
            float a = asS[na][m];
            acc0 = fmaf(a, woS[m][gp],   acc0);
            acc1 = fmaf(a, woS[m][gp+1], acc1);
        }
        __syncthreads();
    }
    atomicAdd(&g_small[OFF_X2 + (n0+na)*16 + gp],   acc0);
    atomicAdd(&g_small[OFF_X2 + (n0+na)*16 + gp+1], acc1);
}

// ---------------- bn1 stats ----------------
__global__ void k_bn1stats(){
    int t = threadIdx.x;
    int col = t&15, rg = t>>4;
    float s = 0.f, ss = 0.f;
    for(int r=0;r<128;r++){
        float v = g_small[OFF_X2 + (rg*128 + r)*16 + col];
        s += v; ss += v*v;
    }
    __shared__ float S[16][17], SS[16][17];
    S[rg][col] = s; SS[rg][col] = ss;
    __syncthreads();
    if(t < 16){
        float a = 0.f, b = 0.f;
        for(int q=0;q<16;q++){ a += S[q][t]; b += SS[q][t]; }
        float m = a / (float)NND;
        float var = b / (float)NND - m*m;
        g_mean[t] = m;
        g_rstd[t] = rsqrtf(var + 1e-5f);
    }
}

// ---------------- per-node tail ----------------
__global__ void k_tail1(const float* __restrict__ bn1g, const float* __restrict__ bn1b,
                        const float* __restrict__ bss, const float* __restrict__ bsh,
                        const float* __restrict__ m1w1, const float* __restrict__ m1b1,
                        const float* __restrict__ m1w2, const float* __restrict__ m1b2,
                        const int* __restrict__ gidx, const int* __restrict__ didx){
    int t = threadIdx.x;
    int w = t>>5, l = t&31;
    int n = blockIdx.x*8 + w;
    __shared__ float xsS[8][17], g1S[8][65];
    int di = didx[n];
    if(l < 16){
        float v = g_small[OFF_X2 + n*16 + l];
        float xb = elu1((v - g_mean[l]) * g_rstd[l] * bn1g[l] + bn1b[l]);
        float xs = xb * bss[di*16 + l] + bsh[di*16 + l];
        xsS[w][l] = fmaxf(xs, 0.f);
    }
    __syncwarp();
    float a0 = m1b1[l], a1 = m1b1[l+32];
    #pragma unroll
    for(int k=0;k<16;k++){
        float x = xsS[w][k];
        a0 = fmaf(x, m1w1[k*64 + l],      a0);
        a1 = fmaf(x, m1w1[k*64 + l + 32], a1);
    }
    g1S[w][l]    = fmaxf(a0, 0.f);
    g1S[w][l+32] = fmaxf(a1, 0.f);
    __syncwarp();
    float c0 = m1b2[l], c1 = m1b2[l+32];
    #pragma unroll 8
    for(int k=0;k<64;k++){
        float x = g1S[w][k];
        c0 = fmaf(x, m1w2[k*64 + l],      c0);
        c1 = fmaf(x, m1w2[k*64 + l + 32], c1);
    }
    float ns = c1 * (1.f / (1.f + expf(-c0)));
    atomicAdd(&g_small[OFF_GS + gidx[n]*32 + l], ns);
}

// ---------------- graph-level tail ----------------
__global__ void k_tail2(const float* __restrict__ m2w1, const float* __restrict__ m2b1,
                        const float* __restrict__ m2w2, const float* __restrict__ m2b2,
                        const float* __restrict__ bn2g, const float* __restrict__ bn2b,
                        float* __restrict__ dout){
    int t = threadIdx.x;
    __shared__ float r1S[8][33], r2S[8][17];
    {
        int g = t>>5, j = t&31;
        float v = m2b1[j];
        #pragma unroll
        for(int k=0;k<32;k++)
            v = fmaf(g_small[OFF_GS + g*32 + k], m2w1[k*32 + j], v);
        r1S[g][j] = fmaxf(v, 0.f);
    }
    __syncthreads();
    if(t < 128){
        int g = t>>4, j = t&15;
        float v = m2b2[j];
        #pragma unroll
        for(int k=0;k<32;k++)
            v = fmaf(r1S[g][k], m2w2[k*16 + j], v);
        r2S[g][j] = v;
    }
    __syncthreads();
    if(t < 16){
        float m = 0.f;
        for(int g=0;g<8;g++) m += r2S[g][t];
        m *= 0.125f;
        float var = 0.f;
        for(int g=0;g<8;g++){ float d = r2S[g][t] - m; var += d*d; }
        var *= 0.125f;
        float rs = rsqrtf(var + 1e-5f);
        for(int g=0;g<8;g++)
            dout[g*16 + t] = (r2S[g][t] - m) * rs * bn2g[t] + bn2b[t];
    }
}

// ---------------- launch ----------------
extern "C" void kernel_launch(void* const* d_in, const int* in_sizes, int n_in,
                              void* d_out, int out_size) {
    const float* X      = (const float*)d_in[0];
    const float* ef     = (const float*)d_in[1];
    const float* Wheads = (const float*)d_in[2];
    const float* aheads = (const float*)d_in[3];
    const float* Wout   = (const float*)d_in[4];
    const float* aout   = (const float*)d_in[5];
    const float* bn1g   = (const float*)d_in[6];
    const float* bn1b   = (const float*)d_in[7];
    const float* bss    = (const float*)d_in[8];
    const float* bsh    = (const float*)d_in[9];
    const float* m1w1   = (const float*)d_in[10];
    const float* m1b1   = (const float*)d_in[11];
    const float* m1w2   = (const float*)d_in[12];
    const float* m1b2   = (const float*)d_in[13];
    const float* m2w1   = (const float*)d_in[14];
    const float* m2b1   = (const float*)d_in[15];
    const float* m2w2   = (const float*)d_in[16];
    const float* m2b2   = (const float*)d_in[17];
    const float* bn2g   = (const float*)d_in[18];
    const float* bn2b   = (const float*)d_in[19];
    const int*   gidx   = (const int*)d_in[20];
    const int*   didx   = (const int*)d_in[21];
    float* dout = (float*)d_out;
    (void)in_sizes; (void)n_in; (void)out_size;

    cudaFuncSetAttribute(k_headmm_mma, cudaFuncAttributeMaxDynamicSharedMemorySize, OF_TOT);

    k_zero<<<(SMALL_TOTAL+255)/256, 256>>>();
    k_wh<<<dim3(512,4), 256>>>(X, Wheads, aheads);
    k_whsplit<<<dim3(64,4), 256>>>();
    k_rawA<<<256, 256>>>((const float4*)ef);
    k_params<<<4, 256>>>(0);
    k_headA<<<256, 256>>>((const float4*)ef);
    k_headB<<<dim3(64,4), 256>>>();
    k_params<<<16, 256>>>(1);
    k_headmm_mma<<<dim3(64,2), 512, OF_TOT>>>();
    k_whout<<<2048, 256>>>(Wout);
    k_s12o<<<8, 256>>>(aout);
    k_outA<<<256, 256>>>(dout);
    k_params<<<4, 256>>>(2);
    k_outmm<<<dim3(64,4), 256>>>(dout);
    k_bn1stats<<<1, 256>>>();
    k_tail1<<<256, 256>>>(bn1g, bn1b, bss, bsh, m1w1, m1b1, m1w2, m1b2, gidx, didx);
    k_tail2<<<1, 256>>>(m2w1, m2b1, m2w2, m2b2, bn2g, bn2b, dout);
}

// round 14
// speedup vs baseline: 1.0888x; 1.0888x over previous
#include <cuda_runtime.h>
#include <cuda_bf16.h>
#include <math.h>
#include <stdint.h>

#define NND 2048
#define NNE (NND*NND)

// ---------------- device scratch ----------------
__device__ float g_Wh[4*NND*64];
__device__ unsigned short g_WhTh[4*64*NND], g_WhTl[4*64*NND];
__device__ float g_s1[4*NND], g_s2[4*NND];
__device__ float g_Whout[NND*16];
__device__ float g_s1o[NND], g_s2o[NND];
__device__ float g_hpA[NND*1024], g_hpB[NND*1024];
__device__ float g_u0[4*NND], g_w0[4*NND], g_il0[4];
__device__ float g_uh[16*NND], g_wh2[16*NND], g_ilh[16];
__device__ float g_uo[4*NND], g_wo[4*NND], g_ilo[4];
__device__ float g_mean[16], g_rstd[16];

#define OFF_RC0 0
#define OFF_RR0 (4*NND)
#define OFF_HC  (8*NND)
#define OFF_HR  (24*NND)
#define OFF_OC  (40*NND)
#define OFF_OR  (44*NND)
#define OFF_GS  (48*NND)
#define OFF_X2  (48*NND+256)
#define SMALL_TOTAL (48*NND+256+NND*16)
__device__ float g_small[SMALL_TOTAL];

__device__ __forceinline__ float wred(float v){
    v += __shfl_down_sync(0xffffffffu, v, 16);
    v += __shfl_down_sync(0xffffffffu, v, 8);
    v += __shfl_down_sync(0xffffffffu, v, 4);
    v += __shfl_down_sync(0xffffffffu, v, 2);
    v += __shfl_down_sync(0xffffffffu, v, 1);
    return v;
}
__device__ __forceinline__ float leaky(float x){ return x > 0.f ? x : 0.2f*x; }
__device__ __forceinline__ float elu1(float x){ return x > 0.f ? x : (expf(x)-1.f); }
__device__ __forceinline__ unsigned short bfh(float x){ return __bfloat16_as_ushort(__float2bfloat16(x)); }
__device__ __forceinline__ float bff(unsigned short u){ return __bfloat162float(__ushort_as_bfloat16(u)); }

__device__ __forceinline__ uint32_t smem_u32(const void* p){
    uint32_t a; asm("{ .reg .u64 t; cvta.to.shared.u64 t, %1; cvt.u32.u64 %0, t; }" : "=r"(a) : "l"(p)); return a;
}
__device__ __forceinline__ void ldmx4(uint32_t* r, uint32_t addr){
    asm volatile("ldmatrix.sync.aligned.m8n8.x4.shared.b16 {%0,%1,%2,%3},[%4];"
        : "=r"(r[0]),"=r"(r[1]),"=r"(r[2]),"=r"(r[3]) : "r"(addr));
}
__device__ __forceinline__ void mmabf(float* d, const uint32_t* a, const uint32_t* b){
    asm volatile("mma.sync.aligned.m16n8k16.row.col.f32.bf16.bf16.f32 "
        "{%0,%1,%2,%3},{%4,%5,%6,%7},{%8,%9},{%0,%1,%2,%3};"
        : "+f"(d[0]),"+f"(d[1]),"+f"(d[2]),"+f"(d[3])
        : "r"(a[0]),"r"(a[1]),"r"(a[2]),"r"(a[3]),"r"(b[0]),"r"(b[1]));
}

// smem layout for headmm (bytes). att row stride 80B (32 bf16 + 8 pad).
#define OF_AH 0
#define OF_AL 40960
#define OF_B  81920
#define OF_W  122880
#define OF_S2 124928
#define OF_W0 125440
#define OF_U  125952
#define OF_IL 128000
#define OF_TOT 128064

// ---------------- zero ----------------
__global__ void k_zero(){
    int i = blockIdx.x*256 + threadIdx.x;
    if(i < SMALL_TOTAL) g_small[i] = 0.f;
}

// ---------------- Wh = X @ W_heads[h] (+ fused s1/s2) ----------------
__global__ void k_wh(const float* __restrict__ X, const float* __restrict__ W,
                     const float* __restrict__ ah){
    int h = blockIdx.y;
    int nb = blockIdx.x*4;
    int t = threadIdx.x;
    __shared__ float Xs[4][128];
    __shared__ float aS[4][64];
    #pragma unroll
    for(int q=0;q<2;q++){
        int idx = t + q*256;
        Xs[idx>>7][idx&127] = X[(size_t)(nb + (idx>>7))*128 + (idx&127)];
    }
    __syncthreads();
    int nl = t>>6, f = t&63;
    float a = 0.f;
    #pragma unroll 16
    for(int k=0;k<128;k++)
        a = fmaf(Xs[nl][k], W[((size_t)h*128 + k)*64 + f], a);
    g_Wh[((size_t)h*NND + nb + nl)*64 + f] = a;
    aS[nl][f] = a;
    __syncthreads();
    int w = t>>5, l = t&31;
    if(w < 4){
        float v0 = aS[w][l], v1 = aS[w][l+32];
        float s1 = fmaf(v0, ah[h*128 + l],      v1*ah[h*128 + l + 32]);
        float s2 = fmaf(v0, ah[h*128 + 64 + l], v1*ah[h*128 + 96 + l]);
        s1 = wred(s1); s2 = wred(s2);
        if(l == 0){
            g_s1[h*NND + nb + w] = s1;
            g_s2[h*NND + nb + w] = s2;
        }
    }
}

// ---------------- WhT hi/lo split (smem transpose, coalesced both ways) ----------------
__global__ void k_whsplit(){
    int h = blockIdx.y;
    int m0 = blockIdx.x*32;
    __shared__ float tile[32][65];
    int t = threadIdx.x;
    #pragma unroll
    for(int q=0;q<8;q++){
        int idx = t + q*256;
        tile[idx>>6][idx&63] = g_Wh[((size_t)h*NND + m0 + (idx>>6))*64 + (idx&63)];
    }
    __syncthreads();
    #pragma unroll
    for(int q=0;q<8;q++){
        int idx = t + q*256;
        int f = idx>>5, m = idx&31;
        float v = tile[m][f];
        unsigned short hi = bfh(v);
        g_WhTh[(size_t)(h*64+f)*NND + m0 + m] = hi;
        g_WhTl[(size_t)(h*64+f)*NND + m0 + m] = bfh(v - bff(hi));
    }
}

// ---------------- raw ef sums: rows + cols fused ----------------
__global__ void k_rawA(const float4* __restrict__ ef){
    __shared__ float rp[4][8][9];
    int t = threadIdx.x, w = t>>5;
    int i0 = blockIdx.x*8;
    float colacc[8][4];
    #pragma unroll
    for(int jb=0;jb<8;jb++)
        #pragma unroll
        for(int c=0;c<4;c++) colacc[jb][c] = 0.f;
    for(int ii=0; ii<8; ii++){
        int i = i0 + ii;
        float a0=0.f,a1=0.f,a2=0.f,a3=0.f;
        #pragma unroll
        for(int jb=0;jb<8;jb++){
            float4 v = ef[(size_t)i*NND + jb*256 + t];
            a0+=v.x; a1+=v.y; a2+=v.z; a3+=v.w;
            colacc[jb][0]+=v.x; colacc[jb][1]+=v.y; colacc[jb][2]+=v.z; colacc[jb][3]+=v.w;
        }
        float r0=wred(a0), r1=wred(a1), r2=wred(a2), r3=wred(a3);
        if((t&31)==0){ rp[0][ii][w]=r0; rp[1][ii][w]=r1; rp[2][ii][w]=r2; rp[3][ii][w]=r3; }
    }
    __syncthreads();
    if(t < 32){
        int c = t>>3, ii = t&7;
        float s = 0.f;
        for(int q=0;q<8;q++) s += rp[c][ii][q];
        g_small[OFF_RR0 + c*NND + i0 + ii] = s;
    }
    #pragma unroll
    for(int jb=0;jb<8;jb++){
        int j = jb*256 + t;
        atomicAdd(&g_small[OFF_RC0 + 0*NND + j], colacc[jb][0]);
        atomicAdd(&g_small[OFF_RC0 + 1*NND + j], colacc[jb][1]);
        atomicAdd(&g_small[OFF_RC0 + 2*NND + j], colacc[jb][2]);
        atomicAdd(&g_small[OFF_RC0 + 3*NND + j], colacc[jb][3]);
    }
}

// ---------------- dsn params ----------------
__global__ void k_params(int mode){
    int ch = blockIdx.x, t = threadIdx.x;
    const float *rs, *cs; float *u, *w, *il;
    if(mode==0){ rs=g_small+OFF_RR0+ch*NND; cs=g_small+OFF_RC0+ch*NND; u=g_u0+ch*NND; w=g_w0+ch*NND; il=g_il0+ch; }
    else if(mode==1){ rs=g_small+OFF_HR+ch*NND; cs=g_small+OFF_HC+ch*NND; u=g_uh+ch*NND; w=g_wh2+ch*NND; il=g_ilh+ch; }
    else { rs=g_small+OFF_OR+ch*NND; cs=g_small+OFF_OC+ch*NND; u=g_uo+ch*NND; w=g_wo+ch*NND; il=g_ilo+ch; }
    __shared__ float smx[256], ssm[256];
    __shared__ float lamS, irS, ilS;
    float mx = -3.4e38f, sm = 0.f;
    #pragma unroll
    for(int q=0;q<8;q++){
        float a = rs[t + q*256]; mx = fmaxf(mx, a); sm += a;
        float b = cs[t + q*256]; mx = fmaxf(mx, b);
    }
    smx[t] = mx; ssm[t] = sm;
    __syncthreads();
    for(int s=128; s; s>>=1){
        if(t < s){ smx[t] = fmaxf(smx[t], smx[t+s]); ssm[t] += ssm[t+s]; }
        __syncthreads();
    }
    if(t==0){
        float lam = smx[0];
        float r = (float)NND*lam - ssm[0];
        lamS = lam; irS = 1.f/r; ilS = 1.f/lam;
        il[0] = ilS;
    }
    __syncthreads();
    float lam = lamS, ir = irS, ilv = ilS;
    #pragma unroll
    for(int q=0;q<8;q++){
        int i = t + q*256;
        u[i] = (lam - rs[i]) * ir;
        w[i] = (lam - cs[i]) * ilv;
    }
}

// ---------------- head row sums (reads ef, inline dsn0; no A0 write) ----------------
__global__ void k_headA(const float4* __restrict__ ef){
    __shared__ float rp[16][8][9];
    int t = threadIdx.x, w = t>>5;
    int i0 = blockIdx.x*8;
    float il0v[4];
    #pragma unroll
    for(int c=0;c<4;c++) il0v[c] = g_il0[c];
    for(int ii=0; ii<8; ii++){
        int i = i0 + ii;
        float s1v[4], u0v[4];
        #pragma unroll
        for(int h=0;h<4;h++) s1v[h] = g_s1[h*NND + i];
        #pragma unroll
        for(int c=0;c<4;c++) u0v[c] = g_u0[c*NND + i];
        float acc[16];
        #pragma unroll
        for(int k=0;k<16;k++) acc[k] = 0.f;
        #pragma unroll 2
        for(int jb=0;jb<8;jb++){
            int j = jb*256 + t;
            float4 tv = ef[(size_t)i*NND + j];
            float tt[4] = {tv.x, tv.y, tv.z, tv.w};
            float A[4];
            #pragma unroll
            for(int c=0;c<4;c++){
                float w0 = g_w0[c*NND + j];
                A[c] = tt[c] > 0.f ? fmaf(tt[c], il0v[c], u0v[c]*w0) : tt[c];
            }
            float P = 1.f;
            #pragma unroll
            for(int h=0;h<4;h++){
                P *= leaky(s1v[h] + g_s2[h*NND + j]);
                #pragma unroll
                for(int c=0;c<4;c++) acc[h*4+c] += A[c]*P;
            }
        }
        #pragma unroll
        for(int k=0;k<16;k++){
            float r = wred(acc[k]);
            if((t&31)==0) rp[k][ii][w] = r;
        }
    }
    __syncthreads();
    if(t < 128){
        int k = t>>3, ii = t&7;
        float s = 0.f;
        for(int q=0;q<8;q++) s += rp[k][ii][q];
        g_small[OFF_HR + k*NND + i0 + ii] = s;
    }
}

// ---------------- head col sums (reads ef, inline dsn0) ----------------
__global__ void k_headB(const float4* __restrict__ ef){
    __shared__ float cs[8][16][33];
    int t = threadIdx.x;
    int jl = t&31, ig = t>>5;
    int j = blockIdx.x*32 + jl;
    int ibase = blockIdx.y*512 + ig*64;
    float s2v[4], w0v[4], il0v[4];
    #pragma unroll
    for(int h=0;h<4;h++) s2v[h] = g_s2[h*NND + j];
    #pragma unroll
    for(int c=0;c<4;c++){ w0v[c] = g_w0[c*NND + j]; il0v[c] = g_il0[c]; }
    float acc[16];
    #pragma unroll
    for(int k=0;k<16;k++) acc[k] = 0.f;
    for(int r=0;r<64;r++){
        int i = ibase + r;
        float4 tv = ef[(size_t)i*NND + j];
        float tt[4] = {tv.x, tv.y, tv.z, tv.w};
        float A[4];
        #pragma unroll
        for(int c=0;c<4;c++){
            float u0 = g_u0[c*NND + i];
            A[c] = tt[c] > 0.f ? fmaf(tt[c], il0v[c], u0*w0v[c]) : tt[c];
        }
        float P = 1.f;
        #pragma unroll
        for(int h=0;h<4;h++){
            P *= leaky(g_s1[h*NND + i] + s2v[h]);
            #pragma unroll
            for(int c=0;c<4;c++) acc[h*4+c] += A[c]*P;
        }
    }
    #pragma unroll
    for(int k=0;k<16;k++) cs[ig][k][jl] = acc[k];
    __syncthreads();
    #pragma unroll
    for(int q=0;q<2;q++){
        int idx = t + q*256;
        int k = idx>>5, jj = idx&31;
        float s = 0.f;
        for(int g=0;g<8;g++) s += cs[g][k][jj];
        atomicAdd(&g_small[OFF_HC + k*NND + blockIdx.x*32 + jj], s);
    }
}

// ---------------- attention @ Wh, all 4 heads per ef read ----------------
__global__ void __launch_bounds__(512,1) k_headmm_mma(const float4* __restrict__ ef){
    extern __shared__ char sm[];
    int t = threadIdx.x;
    int n0g = blockIdx.x*32;
    int khalf = blockIdx.y;
    uint32_t sb = smem_u32(sm);

    float* wS  = (float*)(sm + OF_W);
    float* s2S = (float*)(sm + OF_S2);
    float* w0S = (float*)(sm + OF_W0);
    float* uS  = (float*)(sm + OF_U);
    float* ilS = (float*)(sm + OF_IL);

    if(t < 512){
        int combo = t>>5, n = t&31;
        uS[combo*32 + n] = g_uh[combo*NND + n0g + n];
    }
    if(t < 16) ilS[t] = g_ilh[t];

    int bn = t>>4;
    int bm = (t&15)*2;
    float s1v[4], u0v[4], il0v[4];
    #pragma unroll
    for(int mh=0; mh<4; mh++) s1v[mh] = g_s1[mh*NND + n0g + bn];
    #pragma unroll
    for(int c=0; c<4; c++){ u0v[c] = g_u0[c*NND + n0g + bn]; il0v[c] = g_il0[c]; }

    float acc[2][8][4];
    #pragma unroll
    for(int a=0;a<2;a++)
        #pragma unroll
        for(int b=0;b<8;b++)
            #pragma unroll
            for(int q=0;q<4;q++) acc[a][b][q] = 0.f;

    int wI = t>>5, l = t&31;
    int wh = wI>>2, wc = wI&3;
    int lr = l&15, lc = l>>4;
    uint32_t aBaseH = sb + OF_AH + wI*2560;
    uint32_t aBaseL = sb + OF_AL + wI*2560;
    uint32_t bBaseH = sb + OF_B + (wh*2+0)*5120;
    uint32_t bBaseL = sb + OF_B + (wh*2+1)*5120;
    uint32_t bf = (uint32_t)((l&7) + ((l>>4)<<3));

    for(int ck=0; ck<32; ck++){
        int m0 = khalf*1024 + ck*32;
        __syncthreads();
        wS[t&511] = g_wh2[(t>>5)*NND + m0 + (t&31)];
        if(t < 128){
            s2S[t] = g_s2[(t>>5)*NND + m0 + (t&31)];
            w0S[t] = g_w0[(t>>5)*NND + m0 + (t&31)];
        }
        if(t < 256){
            int h = t>>6, f = t&63;
            const uint4* ph = (const uint4*)&g_WhTh[(size_t)(h*64+f)*NND + m0];
            const uint4* pl = (const uint4*)&g_WhTl[(size_t)(h*64+f)*NND + m0];
            uint4* dh = (uint4*)(sm + OF_B + (h*2+0)*5120 + f*80);
            uint4* dl = (uint4*)(sm + OF_B + (h*2+1)*5120 + f*80);
            dh[0]=ph[0]; dh[1]=ph[1]; dh[2]=ph[2]; dh[3]=ph[3];
            dl[0]=pl[0]; dl[1]=pl[1]; dl[2]=pl[2]; dl[3]=pl[3];
        }
        __syncthreads();
        {
            const float4* ap = ef + (size_t)(n0g+bn)*NND + m0 + bm;
            float4 Ta = ap[0], Tb = ap[1];
            float Tav[4] = {Ta.x, Ta.y, Ta.z, Ta.w};
            float Tbv[4] = {Tb.x, Tb.y, Tb.z, Tb.w};
            float Aav[4], Abv[4];
            #pragma unroll
            for(int c=0;c<4;c++){
                Aav[c] = Tav[c] > 0.f ? fmaf(Tav[c], il0v[c], u0v[c]*w0S[c*32 + bm])     : Tav[c];
                Abv[c] = Tbv[c] > 0.f ? fmaf(Tbv[c], il0v[c], u0v[c]*w0S[c*32 + bm + 1]) : Tbv[c];
            }
            float Pa = 1.f, Pb = 1.f;
            float Pah[4], Pbh[4];
            #pragma unroll
            for(int mh=0; mh<4; mh++){
                Pa *= leaky(s1v[mh] + s2S[mh*32 + bm]);
                Pb *= leaky(s1v[mh] + s2S[mh*32 + bm + 1]);
                Pah[mh] = Pa; Pbh[mh] = Pb;
            }
            uint32_t off = (uint32_t)(bn*80 + bm*2);
            #pragma unroll
            for(int combo=0; combo<16; combo++){
                int h = combo>>2, c = combo&3;
                float il = ilS[combo];
                float uvv = uS[combo*32 + bn];
                float wa = wS[combo*32 + bm], wb = wS[combo*32 + bm + 1];
                float ea = Aav[c]*Pah[h], eb = Abv[c]*Pbh[h];
                float xa = ea > 0.f ? fmaf(ea, il, uvv*wa) : ea;
                float xb = eb > 0.f ? fmaf(eb, il, uvv*wb) : eb;
                unsigned short ha = bfh(xa), hb = bfh(xb);
                uint32_t hw = (uint32_t)ha | ((uint32_t)hb << 16);
                uint32_t lw = (uint32_t)bfh(xa - bff(ha)) | ((uint32_t)bfh(xb - bff(hb)) << 16);
                *(uint32_t*)(sm + OF_AH + combo*2560 + off) = hw;
                *(uint32_t*)(sm + OF_AL + combo*2560 + off) = lw;
            }
        }
        __syncthreads();
        #pragma unroll
        for(int ki=0; ki<2; ki++){
            uint32_t aH[2][4], aL[2][4];
            #pragma unroll
            for(int mi=0; mi<2; mi++){
                uint32_t ro = (uint32_t)((mi*16 + lr)*80 + (ki*16 + lc*8)*2);
                ldmx4(aH[mi], aBaseH + ro);
                ldmx4(aL[mi], aBaseL + ro);
            }
            uint32_t bk = (uint32_t)(ki*16 + ((l>>3)&1)*8);
            #pragma unroll
            for(int np=0; np<4; np++){
                uint32_t bo = (np*16 + bf)*80 + bk*2;
                uint32_t bH[4], bL[4];
                ldmx4(bH, bBaseH + bo);
                ldmx4(bL, bBaseL + bo);
                #pragma unroll
                for(int mi=0; mi<2; mi++){
                    mmabf(acc[mi][np*2],   aH[mi], bH);
                    mmabf(acc[mi][np*2],   aL[mi], bH);
                    mmabf(acc[mi][np*2],   aH[mi], bL);
                    mmabf(acc[mi][np*2+1], aH[mi], bH+2);
                    mmabf(acc[mi][np*2+1], aL[mi], bH+2);
                    mmabf(acc[mi][np*2+1], aH[mi], bL+2);
                }
            }
        }
    }
    float* hpK = khalf == 0 ? g_hpA : g_hpB;
    #pragma unroll
    for(int mi=0; mi<2; mi++){
        int nr = n0g + mi*16 + (l>>2);
        #pragma unroll
        for(int ni=0; ni<8; ni++){
            int f = ni*8 + (l&3)*2;
            float* dst = &hpK[(size_t)nr*1024 + wh*256 + wc*64 + f];
            *(float2*)dst = make_float2(acc[mi][ni][0], acc[mi][ni][1]);
            *(float2*)(dst + 8*1024) = make_float2(acc[mi][ni][2], acc[mi][ni][3]);
        }
    }
}

// ---------------- Whout = elu(hpA+hpB) @ W_out ----------------
__global__ void k_whout(const float* __restrict__ Wout){
    int n = blockIdx.x;
    int t = threadIdx.x;
    __shared__ float eS[1024];
    __shared__ float part[16][17];
    {
        float4 ha = ((const float4*)(g_hpA + (size_t)n*1024))[t];
        float4 hb = ((const float4*)(g_hpB + (size_t)n*1024))[t];
        eS[t*4+0] = elu1(ha.x + hb.x);
        eS[t*4+1] = elu1(ha.y + hb.y);
        eS[t*4+2] = elu1(ha.z + hb.z);
        eS[t*4+3] = elu1(ha.w + hb.w);
    }
    __syncthreads();
    int g = t&15, kg = t>>4;
    float s = 0.f;
    #pragma unroll 8
    for(int k=0;k<64;k++)
        s = fmaf(eS[kg*64+k], Wout[(size_t)(kg*64+k)*16 + g], s);
    part[kg][g] = s;
    __syncthreads();
    if(t < 16){
        float a = 0.f;
        for(int q=0;q<16;q++) a += part[q][t];
        g_Whout[n*16 + t] = a;
    }
}

__global__ void k_s12o(const float* __restrict__ aout){
    int n = blockIdx.x*256 + threadIdx.x;
    float s1 = 0.f, s2 = 0.f;
    #pragma unroll
    for(int g=0;g<16;g++){
        float v = g_Whout[n*16+g];
        s1 = fmaf(v, aout[g],    s1);
        s2 = fmaf(v, aout[16+g], s2);
    }
    g_s1o[n] = s1; g_s2o[n] = s2;
}

// ---------------- out-layer e: write edge_attr + row/col sums fused (reads ef) ----------------
__global__ void k_outA(const float4* __restrict__ ef, float* __restrict__ dout){
    __shared__ float rp[4][8][9];
    int t = threadIdx.x, w = t>>5;
    int i0 = blockIdx.x*8;
    float* eo = dout + 128;
    float il0v[4];
    #pragma unroll
    for(int c=0;c<4;c++) il0v[c] = g_il0[c];
    float colacc[8][4];
    #pragma unroll
    for(int jb=0;jb<8;jb++)
        #pragma unroll
        for(int c=0;c<4;c++) colacc[jb][c] = 0.f;
    for(int ii=0; ii<8; ii++){
        int i = i0 + ii;
        float s1v[4], u0v[4];
        #pragma unroll
        for(int h=0;h<4;h++) s1v[h] = g_s1[h*NND + i];
        #pragma unroll
        for(int c=0;c<4;c++) u0v[c] = g_u0[c*NND + i];
        float s1ov = g_s1o[i];
        float a0=0.f,a1=0.f,a2=0.f,a3=0.f;
        #pragma unroll
        for(int jb=0;jb<8;jb++){
            int j = jb*256 + t;
            float4 tv = ef[(size_t)i*NND + j];
            float tt[4] = {tv.x, tv.y, tv.z, tv.w};
            float A[4];
            #pragma unroll
            for(int c=0;c<4;c++){
                float w0 = g_w0[c*NND + j];
                A[c] = tt[c] > 0.f ? fmaf(tt[c], il0v[c], u0v[c]*w0) : tt[c];
            }
            float P = 1.f;
            #pragma unroll
            for(int h=0;h<4;h++) P *= leaky(s1v[h] + g_s2[h*NND + j]);
            P *= leaky(s1ov + g_s2o[j]);
            float e0 = A[0]*P, e1 = A[1]*P, e2 = A[2]*P, e3 = A[3]*P;
            eo[0u*NNE + (size_t)i*NND + j] = e0;
            eo[1u*NNE + (size_t)i*NND + j] = e1;
            eo[2u*NNE + (size_t)i*NND + j] = e2;
            eo[3u*NNE + (size_t)i*NND + j] = e3;
            a0 += e0; a1 += e1; a2 += e2; a3 += e3;
            colacc[jb][0]+=e0; colacc[jb][1]+=e1; colacc[jb][2]+=e2; colacc[jb][3]+=e3;
        }
        float r0=wred(a0), r1=wred(a1), r2=wred(a2), r3=wred(a3);
        if((t&31)==0){ rp[0][ii][w]=r0; rp[1][ii][w]=r1; rp[2][ii][w]=r2; rp[3][ii][w]=r3; }
    }
    __syncthreads();
    if(t < 32){
        int c = t>>3, ii = t&7;
        float s = 0.f;
        for(int q=0;q<8;q++) s += rp[c][ii][q];
        g_small[OFF_OR + c*NND + i0 + ii] = s;
    }
    #pragma unroll
    for(int jb=0;jb<8;jb++){
        int j = jb*256 + t;
        atomicAdd(&g_small[OFF_OC + 0*NND + j], colacc[jb][0]);
        atomicAdd(&g_small[OFF_OC + 1*NND + j], colacc[jb][1]);
        atomicAdd(&g_small[OFF_OC + 2*NND + j], colacc[jb][2]);
        atomicAdd(&g_small[OFF_OC + 3*NND + j], colacc[jb][3]);
    }
}

// ---------------- out-layer: x2 = sum_c dsn(eo_c) @ Whout (reads stored e) ----------------
__global__ void k_outmm(const float* __restrict__ dout){
    int n0 = blockIdx.x*32;
    int kbase = blockIdx.y*512;
    int t = threadIdx.x;
    __shared__ float asS[32][33];
    __shared__ float woS[32][16];
    __shared__ float uoS[4][32], iloS[4];
    const float* eo = dout + 128;
    if(t < 32){
        #pragma unroll
        for(int c=0;c<4;c++) uoS[c][t] = g_uo[c*NND + n0 + t];
    }
    if(t < 4) iloS[t] = g_ilo[t];
    int bn = t>>3, bm4 = (t&7)*4;
    int na = t>>3, gp = (t&7)*2;
    float acc0 = 0.f, acc1 = 0.f;
    __syncthreads();
    for(int mt=0; mt<16; mt++){
        int m0 = kbase + mt*32;
        ((float*)woS)[t]       = g_Whout[(size_t)m0*16 + t];
        ((float*)woS)[t+256]   = g_Whout[(size_t)m0*16 + t + 256];
        #pragma unroll
        for(int k=0;k<4;k++){
            int m = bm4 + k, mg = m0 + m;
            size_t base = (size_t)(n0+bn)*NND + mg;
            float s = 0.f;
            #pragma unroll
            for(int c=0;c<4;c++){
                float e = eo[(size_t)c*NNE + base];
                float wv = g_wo[c*NND + mg];
                s += e > 0.f ? fmaf(e, iloS[c], uoS[c][bn]*wv) : e;
            }
            asS[bn][m] = s;
        }
        __syncthreads();
        #pragma unroll 8
        for(int m=0;m<32;m++){
            float a = asS[na][m];
            acc0 = fmaf(a, woS[m][gp],   acc0);
            acc1 = fmaf(a, woS[m][gp+1], acc1);
        }
        __syncthreads();
    }
    atomicAdd(&g_small[OFF_X2 + (n0+na)*16 + gp],   acc0);
    atomicAdd(&g_small[OFF_X2 + (n0+na)*16 + gp+1], acc1);
}

// ---------------- bn1 stats ----------------
__global__ void k_bn1stats(){
    int t = threadIdx.x;
    int col = t&15, rg = t>>4;
    float s = 0.f, ss = 0.f;
    for(int r=0;r<128;r++){
        float v = g_small[OFF_X2 + (rg*128 + r)*16 + col];
        s += v; ss += v*v;
    }
    __shared__ float S[16][17], SS[16][17];
    S[rg][col] = s; SS[rg][col] = ss;
    __syncthreads();
    if(t < 16){
        float a = 0.f, b = 0.f;
        for(int q=0;q<16;q++){ a += S[q][t]; b += SS[q][t]; }
        float m = a / (float)NND;
        float var = b / (float)NND - m*m;
        g_mean[t] = m;
        g_rstd[t] = rsqrtf(var + 1e-5f);
    }
}

// ---------------- per-node tail ----------------
__global__ void k_tail1(const float* __restrict__ bn1g, const float* __restrict__ bn1b,
                        const float* __restrict__ bss, const float* __restrict__ bsh,
                        const float* __restrict__ m1w1, const float* __restrict__ m1b1,
                        const float* __restrict__ m1w2, const float* __restrict__ m1b2,
                        const int* __restrict__ gidx, const int* __restrict__ didx){
    int t = threadIdx.x;
    int w = t>>5, l = t&31;
    int n = blockIdx.x*8 + w;
    __shared__ float xsS[8][17], g1S[8][65];
    int di = didx[n];
    if(l < 16){
        float v = g_small[OFF_X2 + n*16 + l];
        float xb = elu1((v - g_mean[l]) * g_rstd[l] * bn1g[l] + bn1b[l]);
        float xs = xb * bss[di*16 + l] + bsh[di*16 + l];
        xsS[w][l] = fmaxf(xs, 0.f);
    }
    __syncwarp();
    float a0 = m1b1[l], a1 = m1b1[l+32];
    #pragma unroll
    for(int k=0;k<16;k++){
        float x = xsS[w][k];
        a0 = fmaf(x, m1w1[k*64 + l],      a0);
        a1 = fmaf(x, m1w1[k*64 + l + 32], a1);
    }
    g1S[w][l]    = fmaxf(a0, 0.f);
    g1S[w][l+32] = fmaxf(a1, 0.f);
    __syncwarp();
    float c0 = m1b2[l], c1 = m1b2[l+32];
    #pragma unroll 8
    for(int k=0;k<64;k++){
        float x = g1S[w][k];
        c0 = fmaf(x, m1w2[k*64 + l],      c0);
        c1 = fmaf(x, m1w2[k*64 + l + 32], c1);
    }
    float ns = c1 * (1.f / (1.f + expf(-c0)));
    atomicAdd(&g_small[OFF_GS + gidx[n]*32 + l], ns);
}

// ---------------- graph-level tail ----------------
__global__ void k_tail2(const float* __restrict__ m2w1, const float* __restrict__ m2b1,
                        const float* __restrict__ m2w2, const float* __restrict__ m2b2,
                        const float* __restrict__ bn2g, const float* __restrict__ bn2b,
                        float* __restrict__ dout){
    int t = threadIdx.x;
    __shared__ float r1S[8][33], r2S[8][17];
    {
        int g = t>>5, j = t&31;
        float v = m2b1[j];
        #pragma unroll
        for(int k=0;k<32;k++)
            v = fmaf(g_small[OFF_GS + g*32 + k], m2w1[k*32 + j], v);
        r1S[g][j] = fmaxf(v, 0.f);
    }
    __syncthreads();
    if(t < 128){
        int g = t>>4, j = t&15;
        float v = m2b2[j];
        #pragma unroll
        for(int k=0;k<32;k++)
            v = fmaf(r1S[g][k], m2w2[k*16 + j], v);
        r2S[g][j] = v;
    }
    __syncthreads();
    if(t < 16){
        float m = 0.f;
        for(int g=0;g<8;g++) m += r2S[g][t];
        m *= 0.125f;
        float var = 0.f;
        for(int g=0;g<8;g++){ float d = r2S[g][t] - m; var += d*d; }
        var *= 0.125f;
        float rs = rsqrtf(var + 1e-5f);
        for(int g=0;g<8;g++)
            dout[g*16 + t] = (r2S[g][t] - m) * rs * bn2g[t] + bn2b[t];
    }
}

// ---------------- launch ----------------
extern "C" void kernel_launch(void* const* d_in, const int* in_sizes, int n_in,
                              void* d_out, int out_size) {
    const float* X      = (const float*)d_in[0];
    const float* ef     = (const float*)d_in[1];
    const float* Wheads = (const float*)d_in[2];
    const float* aheads = (const float*)d_in[3];
    const float* Wout   = (const float*)d_in[4];
    const float* aout   = (const float*)d_in[5];
    const float* bn1g   = (const float*)d_in[6];
    const float* bn1b   = (const float*)d_in[7];
    const float* bss    = (const float*)d_in[8];
    const float* bsh    = (const float*)d_in[9];
    const float* m1w1   = (const float*)d_in[10];
    const float* m1b1   = (const float*)d_in[11];
    const float* m1w2   = (const float*)d_in[12];
    const float* m1b2   = (const float*)d_in[13];
    const float* m2w1   = (const float*)d_in[14];
    const float* m2b1   = (const float*)d_in[15];
    const float* m2w2   = (const float*)d_in[16];
    const float* m2b2   = (const float*)d_in[17];
    const float* bn2g   = (const float*)d_in[18];
    const float* bn2b   = (const float*)d_in[19];
    const int*   gidx   = (const int*)d_in[20];
    const int*   didx   = (const int*)d_in[21];
    float* dout = (float*)d_out;
    (void)in_sizes; (void)n_in; (void)out_size;

    cudaFuncSetAttribute(k_headmm_mma, cudaFuncAttributeMaxDynamicSharedMemorySize, OF_TOT);

    k_zero<<<(SMALL_TOTAL+255)/256, 256>>>();
    k_wh<<<dim3(512,4), 256>>>(X, Wheads, aheads);
    k_whsplit<<<dim3(64,4), 256>>>();
    k_rawA<<<256, 256>>>((const float4*)ef);
    k_params<<<4, 256>>>(0);
    k_headA<<<256, 256>>>((const float4*)ef);
    k_headB<<<dim3(64,4), 256>>>((const float4*)ef);
    k_params<<<16, 256>>>(1);
    k_headmm_mma<<<dim3(64,2), 512, OF_TOT>>>((const float4*)ef);
    k_whout<<<2048, 256>>>(Wout);
    k_s12o<<<8, 256>>>(aout);
    k_outA<<<256, 256>>>((const float4*)ef, dout);
    k_params<<<4, 256>>>(2);
    k_outmm<<<dim3(64,4), 256>>>(dout);
    k_bn1stats<<<1, 256>>>();
    k_tail1<<<256, 256>>>(bn1g, bn1b, bss, bsh, m1w1, m1b1, m1w2, m1b2, gidx, didx);
    k_tail2<<<1, 256>>>(m2w1, m2b1, m2w2, m2b2, bn2g, bn2b, dout);
}

// round 15
// speedup vs baseline: 1.1139x; 1.0231x over previous
#include <cuda_runtime.h>
#include <cuda_bf16.h>
#include <math.h>
#include <stdint.h>

#define NND 2048
#define NNE (NND*NND)

// ---------------- device scratch ----------------
__device__ float g_Wh[4*NND*64];
__device__ unsigned short g_WhTh[4*64*NND], g_WhTl[4*64*NND];
__device__ float g_s1[4*NND], g_s2[4*NND];
__device__ float g_Whout[NND*16];
__device__ float g_s1o[NND], g_s2o[NND];
__device__ float g_hpA[NND*1024], g_hpB[NND*1024];
__device__ float g_u0[4*NND], g_w0[4*NND], g_il0[4];
__device__ float g_uh[16*NND], g_wh2[16*NND], g_ilh[16];
__device__ float g_uo[4*NND], g_wo[4*NND], g_ilo[4];
__device__ float g_mean[16], g_rstd[16];

#define OFF_RC0 0
#define OFF_RR0 (4*NND)
#define OFF_HC  (8*NND)
#define OFF_HR  (24*NND)
#define OFF_OC  (40*NND)
#define OFF_OR  (44*NND)
#define OFF_GS  (48*NND)
#define OFF_X2  (48*NND+256)
#define SMALL_TOTAL (48*NND+256+NND*16)
__device__ float g_small[SMALL_TOTAL];

__device__ __forceinline__ float wred(float v){
    v += __shfl_down_sync(0xffffffffu, v, 16);
    v += __shfl_down_sync(0xffffffffu, v, 8);
    v += __shfl_down_sync(0xffffffffu, v, 4);
    v += __shfl_down_sync(0xffffffffu, v, 2);
    v += __shfl_down_sync(0xffffffffu, v, 1);
    return v;
}
__device__ __forceinline__ float leaky(float x){ return x > 0.f ? x : 0.2f*x; }
__device__ __forceinline__ float elu1(float x){ return x > 0.f ? x : (expf(x)-1.f); }
__device__ __forceinline__ unsigned short bfh(float x){ return __bfloat16_as_ushort(__float2bfloat16(x)); }
__device__ __forceinline__ float bff(unsigned short u){ return __bfloat162float(__ushort_as_bfloat16(u)); }

__device__ __forceinline__ uint32_t smem_u32(const void* p){
    uint32_t a; asm("{ .reg .u64 t; cvta.to.shared.u64 t, %1; cvt.u32.u64 %0, t; }" : "=r"(a) : "l"(p)); return a;
}
__device__ __forceinline__ void ldmx4(uint32_t* r, uint32_t addr){
    asm volatile("ldmatrix.sync.aligned.m8n8.x4.shared.b16 {%0,%1,%2,%3},[%4];"
        : "=r"(r[0]),"=r"(r[1]),"=r"(r[2]),"=r"(r[3]) : "r"(addr));
}
__device__ __forceinline__ void mmabf(float* d, const uint32_t* a, const uint32_t* b){
    asm volatile("mma.sync.aligned.m16n8k16.row.col.f32.bf16.bf16.f32 "
        "{%0,%1,%2,%3},{%4,%5,%6,%7},{%8,%9},{%0,%1,%2,%3};"
        : "+f"(d[0]),"+f"(d[1]),"+f"(d[2]),"+f"(d[3])
        : "r"(a[0]),"r"(a[1]),"r"(a[2]),"r"(a[3]),"r"(b[0]),"r"(b[1]));
}

// smem layout for headmm (bytes). att row stride 80B (32 bf16 + 8 pad).
#define OF_AH 0
#define OF_AL 40960
#define OF_B  81920
#define OF_W  122880
#define OF_S2 124928
#define OF_W0 125440
#define OF_U  125952
#define OF_IL 128000
#define OF_TOT 128064

// ---------------- zero ----------------
__global__ void k_zero(){
    int i = blockIdx.x*256 + threadIdx.x;
    if(i < SMALL_TOTAL) g_small[i] = 0.f;
}

// ---------------- Wh = X @ W_heads[h] (+ fused s1/s2) ----------------
__global__ void k_wh(const float* __restrict__ X, const float* __restrict__ W,
                     const float* __restrict__ ah){
    int h = blockIdx.y;
    int nb = blockIdx.x*4;
    int t = threadIdx.x;
    __shared__ float Xs[4][128];
    __shared__ float aS[4][64];
    #pragma unroll
    for(int q=0;q<2;q++){
        int idx = t + q*256;
        Xs[idx>>7][idx&127] = X[(size_t)(nb + (idx>>7))*128 + (idx&127)];
    }
    __syncthreads();
    int nl = t>>6, f = t&63;
    float a = 0.f;
    #pragma unroll 16
    for(int k=0;k<128;k++)
        a = fmaf(Xs[nl][k], W[((size_t)h*128 + k)*64 + f], a);
    g_Wh[((size_t)h*NND + nb + nl)*64 + f] = a;
    aS[nl][f] = a;
    __syncthreads();
    int w = t>>5, l = t&31;
    if(w < 4){
        float v0 = aS[w][l], v1 = aS[w][l+32];
        float s1 = fmaf(v0, ah[h*128 + l],      v1*ah[h*128 + l + 32]);
        float s2 = fmaf(v0, ah[h*128 + 64 + l], v1*ah[h*128 + 96 + l]);
        s1 = wred(s1); s2 = wred(s2);
        if(l == 0){
            g_s1[h*NND + nb + w] = s1;
            g_s2[h*NND + nb + w] = s2;
        }
    }
}

// ---------------- WhT hi/lo split (smem transpose) ----------------
__global__ void k_whsplit(){
    int h = blockIdx.y;
    int m0 = blockIdx.x*32;
    __shared__ float tile[32][65];
    int t = threadIdx.x;
    #pragma unroll
    for(int q=0;q<8;q++){
        int idx = t + q*256;
        tile[idx>>6][idx&63] = g_Wh[((size_t)h*NND + m0 + (idx>>6))*64 + (idx&63)];
    }
    __syncthreads();
    #pragma unroll
    for(int q=0;q<8;q++){
        int idx = t + q*256;
        int f = idx>>5, m = idx&31;
        float v = tile[m][f];
        unsigned short hi = bfh(v);
        g_WhTh[(size_t)(h*64+f)*NND + m0 + m] = hi;
        g_WhTl[(size_t)(h*64+f)*NND + m0 + m] = bfh(v - bff(hi));
    }
}

// ---------------- raw ef sums: rows + cols fused (4 rows/block) ----------------
__global__ void k_rawA(const float4* __restrict__ ef){
    __shared__ float rp[4][4][9];
    int t = threadIdx.x, w = t>>5;
    int i0 = blockIdx.x*4;
    float colacc[8][4];
    #pragma unroll
    for(int jb=0;jb<8;jb++)
        #pragma unroll
        for(int c=0;c<4;c++) colacc[jb][c] = 0.f;
    for(int ii=0; ii<4; ii++){
        int i = i0 + ii;
        float a0=0.f,a1=0.f,a2=0.f,a3=0.f;
        #pragma unroll
        for(int jb=0;jb<8;jb++){
            float4 v = ef[(size_t)i*NND + jb*256 + t];
            a0+=v.x; a1+=v.y; a2+=v.z; a3+=v.w;
            colacc[jb][0]+=v.x; colacc[jb][1]+=v.y; colacc[jb][2]+=v.z; colacc[jb][3]+=v.w;
        }
        float r0=wred(a0), r1=wred(a1), r2=wred(a2), r3=wred(a3);
        if((t&31)==0){ rp[0][ii][w]=r0; rp[1][ii][w]=r1; rp[2][ii][w]=r2; rp[3][ii][w]=r3; }
    }
    __syncthreads();
    if(t < 16){
        int c = t>>2, ii = t&3;
        float s = 0.f;
        for(int q=0;q<8;q++) s += rp[c][ii][q];
        g_small[OFF_RR0 + c*NND + i0 + ii] = s;
    }
    #pragma unroll
    for(int jb=0;jb<8;jb++){
        int j = jb*256 + t;
        atomicAdd(&g_small[OFF_RC0 + 0*NND + j], colacc[jb][0]);
        atomicAdd(&g_small[OFF_RC0 + 1*NND + j], colacc[jb][1]);
        atomicAdd(&g_small[OFF_RC0 + 2*NND + j], colacc[jb][2]);
        atomicAdd(&g_small[OFF_RC0 + 3*NND + j], colacc[jb][3]);
    }
}

// ---------------- dsn params ----------------
__global__ void k_params(int mode){
    int ch = blockIdx.x, t = threadIdx.x;
    const float *rs, *cs; float *u, *w, *il;
    if(mode==0){ rs=g_small+OFF_RR0+ch*NND; cs=g_small+OFF_RC0+ch*NND; u=g_u0+ch*NND; w=g_w0+ch*NND; il=g_il0+ch; }
    else if(mode==1){ rs=g_small+OFF_HR+ch*NND; cs=g_small+OFF_HC+ch*NND; u=g_uh+ch*NND; w=g_wh2+ch*NND; il=g_ilh+ch; }
    else { rs=g_small+OFF_OR+ch*NND; cs=g_small+OFF_OC+ch*NND; u=g_uo+ch*NND; w=g_wo+ch*NND; il=g_ilo+ch; }
    __shared__ float smx[256], ssm[256];
    __shared__ float lamS, irS, ilS;
    float mx = -3.4e38f, sm = 0.f;
    #pragma unroll
    for(int q=0;q<8;q++){
        float a = rs[t + q*256]; mx = fmaxf(mx, a); sm += a;
        float b = cs[t + q*256]; mx = fmaxf(mx, b);
    }
    smx[t] = mx; ssm[t] = sm;
    __syncthreads();
    for(int s=128; s; s>>=1){
        if(t < s){ smx[t] = fmaxf(smx[t], smx[t+s]); ssm[t] += ssm[t+s]; }
        __syncthreads();
    }
    if(t==0){
        float lam = smx[0];
        float r = (float)NND*lam - ssm[0];
        lamS = lam; irS = 1.f/r; ilS = 1.f/lam;
        il[0] = ilS;
    }
    __syncthreads();
    float lam = lamS, ir = irS, ilv = ilS;
    #pragma unroll
    for(int q=0;q<8;q++){
        int i = t + q*256;
        u[i] = (lam - rs[i]) * ir;
        w[i] = (lam - cs[i]) * ilv;
    }
}

// ---------------- head row sums (reads ef, inline dsn0; 4 rows/block) ----------------
__global__ void k_headA(const float4* __restrict__ ef){
    __shared__ float rp[16][4][9];
    int t = threadIdx.x, w = t>>5;
    int i0 = blockIdx.x*4;
    float il0v[4];
    #pragma unroll
    for(int c=0;c<4;c++) il0v[c] = g_il0[c];
    for(int ii=0; ii<4; ii++){
        int i = i0 + ii;
        float s1v[4], u0v[4];
        #pragma unroll
        for(int h=0;h<4;h++) s1v[h] = g_s1[h*NND + i];
        #pragma unroll
        for(int c=0;c<4;c++) u0v[c] = g_u0[c*NND + i];
        float acc[16];
        #pragma unroll
        for(int k=0;k<16;k++) acc[k] = 0.f;
        #pragma unroll 2
        for(int jb=0;jb<8;jb++){
            int j = jb*256 + t;
            float4 tv = ef[(size_t)i*NND + j];
            float tt[4] = {tv.x, tv.y, tv.z, tv.w};
            float A[4];
            #pragma unroll
            for(int c=0;c<4;c++){
                float w0 = g_w0[c*NND + j];
                A[c] = tt[c] > 0.f ? fmaf(tt[c], il0v[c], u0v[c]*w0) : tt[c];
            }
            float P = 1.f;
            #pragma unroll
            for(int h=0;h<4;h++){
                P *= leaky(s1v[h] + g_s2[h*NND + j]);
                #pragma unroll
                for(int c=0;c<4;c++) acc[h*4+c] += A[c]*P;
            }
        }
        #pragma unroll
        for(int k=0;k<16;k++){
            float r = wred(acc[k]);
            if((t&31)==0) rp[k][ii][w] = r;
        }
    }
    __syncthreads();
    if(t < 64){
        int k = t>>2, ii = t&3;
        float s = 0.f;
        for(int q=0;q<8;q++) s += rp[k][ii][q];
        g_small[OFF_HR + k*NND + i0 + ii] = s;
    }
}

// ---------------- head col sums (reads ef, inline dsn0; 256-row chunks) ----------------
__global__ void k_headB(const float4* __restrict__ ef){
    __shared__ float cs[8][16][33];
    int t = threadIdx.x;
    int jl = t&31, ig = t>>5;
    int j = blockIdx.x*32 + jl;
    int ibase = blockIdx.y*256 + ig*32;
    float s2v[4], w0v[4], il0v[4];
    #pragma unroll
    for(int h=0;h<4;h++) s2v[h] = g_s2[h*NND + j];
    #pragma unroll
    for(int c=0;c<4;c++){ w0v[c] = g_w0[c*NND + j]; il0v[c] = g_il0[c]; }
    float acc[16];
    #pragma unroll
    for(int k=0;k<16;k++) acc[k] = 0.f;
    for(int r=0;r<32;r++){
        int i = ibase + r;
        float4 tv = ef[(size_t)i*NND + j];
        float tt[4] = {tv.x, tv.y, tv.z, tv.w};
        float A[4];
        #pragma unroll
        for(int c=0;c<4;c++){
            float u0 = g_u0[c*NND + i];
            A[c] = tt[c] > 0.f ? fmaf(tt[c], il0v[c], u0*w0v[c]) : tt[c];
        }
        float P = 1.f;
        #pragma unroll
        for(int h=0;h<4;h++){
            P *= leaky(g_s1[h*NND + i] + s2v[h]);
            #pragma unroll
            for(int c=0;c<4;c++) acc[h*4+c] += A[c]*P;
        }
    }
    #pragma unroll
    for(int k=0;k<16;k++) cs[ig][k][jl] = acc[k];
    __syncthreads();
    #pragma unroll
    for(int q=0;q<2;q++){
        int idx = t + q*256;
        int k = idx>>5, jj = idx&31;
        float s = 0.f;
        for(int g=0;g<8;g++) s += cs[g][k][jj];
        atomicAdd(&g_small[OFF_HC + k*NND + blockIdx.x*32 + jj], s);
    }
}

// ---------------- attention @ Wh, all 4 heads per ef read ----------------
__global__ void __launch_bounds__(512,1) k_headmm_mma(const float4* __restrict__ ef){
    extern __shared__ char sm[];
    int t = threadIdx.x;
    int n0g = blockIdx.x*32;
    int khalf = blockIdx.y;
    uint32_t sb = smem_u32(sm);

    float* wS  = (float*)(sm + OF_W);
    float* s2S = (float*)(sm + OF_S2);
    float* w0S = (float*)(sm + OF_W0);
    float* uS  = (float*)(sm + OF_U);
    float* ilS = (float*)(sm + OF_IL);

    if(t < 512){
        int combo = t>>5, n = t&31;
        uS[combo*32 + n] = g_uh[combo*NND + n0g + n];
    }
    if(t < 16) ilS[t] = g_ilh[t];

    int bn = t>>4;
    int bm = (t&15)*2;
    float s1v[4], u0v[4], il0v[4];
    #pragma unroll
    for(int mh=0; mh<4; mh++) s1v[mh] = g_s1[mh*NND + n0g + bn];
    #pragma unroll
    for(int c=0; c<4; c++){ u0v[c] = g_u0[c*NND + n0g + bn]; il0v[c] = g_il0[c]; }

    float acc[2][8][4];
    #pragma unroll
    for(int a=0;a<2;a++)
        #pragma unroll
        for(int b=0;b<8;b++)
            #pragma unroll
            for(int q=0;q<4;q++) acc[a][b][q] = 0.f;

    int wI = t>>5, l = t&31;
    int wh = wI>>2, wc = wI&3;
    int lr = l&15, lc = l>>4;
    uint32_t aBaseH = sb + OF_AH + wI*2560;
    uint32_t aBaseL = sb + OF_AL + wI*2560;
    uint32_t bBaseH = sb + OF_B + (wh*2+0)*5120;
    uint32_t bBaseL = sb + OF_B + (wh*2+1)*5120;
    uint32_t bf = (uint32_t)((l&7) + ((l>>4)<<3));

    for(int ck=0; ck<32; ck++){
        int m0 = khalf*1024 + ck*32;
        __syncthreads();
        wS[t&511] = g_wh2[(t>>5)*NND + m0 + (t&31)];
        if(t < 128){
            s2S[t] = g_s2[(t>>5)*NND + m0 + (t&31)];
            w0S[t] = g_w0[(t>>5)*NND + m0 + (t&31)];
        }
        if(t < 256){
            int h = t>>6, f = t&63;
            const uint4* ph = (const uint4*)&g_WhTh[(size_t)(h*64+f)*NND + m0];
            const uint4* pl = (const uint4*)&g_WhTl[(size_t)(h*64+f)*NND + m0];
            uint4* dh = (uint4*)(sm + OF_B + (h*2+0)*5120 + f*80);
            uint4* dl = (uint4*)(sm + OF_B + (h*2+1)*5120 + f*80);
            dh[0]=ph[0]; dh[1]=ph[1]; dh[2]=ph[2]; dh[3]=ph[3];
            dl[0]=pl[0]; dl[1]=pl[1]; dl[2]=pl[2]; dl[3]=pl[3];
        }
        __syncthreads();
        {
            const float4* ap = ef + (size_t)(n0g+bn)*NND + m0 + bm;
            float4 Ta = ap[0], Tb = ap[1];
            float Tav[4] = {Ta.x, Ta.y, Ta.z, Ta.w};
            float Tbv[4] = {Tb.x, Tb.y, Tb.z, Tb.w};
            float Aav[4], Abv[4];
            #pragma unroll
            for(int c=0;c<4;c++){
                Aav[c] = Tav[c] > 0.f ? fmaf(Tav[c], il0v[c], u0v[c]*w0S[c*32 + bm])     : Tav[c];
                Abv[c] = Tbv[c] > 0.f ? fmaf(Tbv[c], il0v[c], u0v[c]*w0S[c*32 + bm + 1]) : Tbv[c];
            }
            float Pa = 1.f, Pb = 1.f;
            float Pah[4], Pbh[4];
            #pragma unroll
            for(int mh=0; mh<4; mh++){
                Pa *= leaky(s1v[mh] + s2S[mh*32 + bm]);
                Pb *= leaky(s1v[mh] + s2S[mh*32 + bm + 1]);
                Pah[mh] = Pa; Pbh[mh] = Pb;
            }
            uint32_t off = (uint32_t)(bn*80 + bm*2);
            #pragma unroll
            for(int combo=0; combo<16; combo++){
                int h = combo>>2, c = combo&3;
                float il = ilS[combo];
                float uvv = uS[combo*32 + bn];
                float wa = wS[combo*32 + bm], wb = wS[combo*32 + bm + 1];
                float ea = Aav[c]*Pah[h], eb = Abv[c]*Pbh[h];
                float xa = ea > 0.f ? fmaf(ea, il, uvv*wa) : ea;
                float xb = eb > 0.f ? fmaf(eb, il, uvv*wb) : eb;
                unsigned short ha = bfh(xa), hb = bfh(xb);
                uint32_t hw = (uint32_t)ha | ((uint32_t)hb << 16);
                uint32_t lw = (uint32_t)bfh(xa - bff(ha)) | ((uint32_t)bfh(xb - bff(hb)) << 16);
                *(uint32_t*)(sm + OF_AH + combo*2560 + off) = hw;
                *(uint32_t*)(sm + OF_AL + combo*2560 + off) = lw;
            }
        }
        __syncthreads();
        #pragma unroll
        for(int ki=0; ki<2; ki++){
            uint32_t aH[2][4], aL[2][4];
            #pragma unroll
            for(int mi=0; mi<2; mi++){
                uint32_t ro = (uint32_t)((mi*16 + lr)*80 + (ki*16 + lc*8)*2);
                ldmx4(aH[mi], aBaseH + ro);
                ldmx4(aL[mi], aBaseL + ro);
            }
            uint32_t bk = (uint32_t)(ki*16 + ((l>>3)&1)*8);
            #pragma unroll
            for(int np=0; np<4; np++){
                uint32_t bo = (np*16 + bf)*80 + bk*2;
                uint32_t bH[4], bL[4];
                ldmx4(bH, bBaseH + bo);
                ldmx4(bL, bBaseL + bo);
                #pragma unroll
                for(int mi=0; mi<2; mi++){
                    mmabf(acc[mi][np*2],   aH[mi], bH);
                    mmabf(acc[mi][np*2],   aL[mi], bH);
                    mmabf(acc[mi][np*2],   aH[mi], bL);
                    mmabf(acc[mi][np*2+1], aH[mi], bH+2);
                    mmabf(acc[mi][np*2+1], aL[mi], bH+2);
                    mmabf(acc[mi][np*2+1], aH[mi], bL+2);
                }
            }
        }
    }
    float* hpK = khalf == 0 ? g_hpA : g_hpB;
    #pragma unroll
    for(int mi=0; mi<2; mi++){
        int nr = n0g + mi*16 + (l>>2);
        #pragma unroll
        for(int ni=0; ni<8; ni++){
            int f = ni*8 + (l&3)*2;
            float* dst = &hpK[(size_t)nr*1024 + wh*256 + wc*64 + f];
            *(float2*)dst = make_float2(acc[mi][ni][0], acc[mi][ni][1]);
            *(float2*)(dst + 8*1024) = make_float2(acc[mi][ni][2], acc[mi][ni][3]);
        }
    }
}

// ---------------- Whout = elu(hpA+hpB) @ W_out ----------------
__global__ void k_whout(const float* __restrict__ Wout){
    int n = blockIdx.x;
    int t = threadIdx.x;
    __shared__ float eS[1024];
    __shared__ float part[16][17];
    {
        float4 ha = ((const float4*)(g_hpA + (size_t)n*1024))[t];
        float4 hb = ((const float4*)(g_hpB + (size_t)n*1024))[t];
        eS[t*4+0] = elu1(ha.x + hb.x);
        eS[t*4+1] = elu1(ha.y + hb.y);
        eS[t*4+2] = elu1(ha.z + hb.z);
        eS[t*4+3] = elu1(ha.w + hb.w);
    }
    __syncthreads();
    int g = t&15, kg = t>>4;
    float s = 0.f;
    #pragma unroll 8
    for(int k=0;k<64;k++)
        s = fmaf(eS[kg*64+k], Wout[(size_t)(kg*64+k)*16 + g], s);
    part[kg][g] = s;
    __syncthreads();
    if(t < 16){
        float a = 0.f;
        for(int q=0;q<16;q++) a += part[q][t];
        g_Whout[n*16 + t] = a;
    }
}

__global__ void k_s12o(const float* __restrict__ aout){
    int n = blockIdx.x*256 + threadIdx.x;
    float s1 = 0.f, s2 = 0.f;
    #pragma unroll
    for(int g=0;g<16;g++){
        float v = g_Whout[n*16+g];
        s1 = fmaf(v, aout[g],    s1);
        s2 = fmaf(v, aout[16+g], s2);
    }
    g_s1o[n] = s1; g_s2o[n] = s2;
}

// ---------------- out-layer e: write edge_attr + row/col sums fused (4 rows/block) ----------------
__global__ void k_outA(const float4* __restrict__ ef, float* __restrict__ dout){
    __shared__ float rp[4][4][9];
    int t = threadIdx.x, w = t>>5;
    int i0 = blockIdx.x*4;
    float* eo = dout + 128;
    float il0v[4];
    #pragma unroll
    for(int c=0;c<4;c++) il0v[c] = g_il0[c];
    float colacc[8][4];
    #pragma unroll
    for(int jb=0;jb<8;jb++)
        #pragma unroll
        for(int c=0;c<4;c++) colacc[jb][c] = 0.f;
    for(int ii=0; ii<4; ii++){
        int i = i0 + ii;
        float s1v[4], u0v[4];
        #pragma unroll
        for(int h=0;h<4;h++) s1v[h] = g_s1[h*NND + i];
        #pragma unroll
        for(int c=0;c<4;c++) u0v[c] = g_u0[c*NND + i];
        float s1ov = g_s1o[i];
        float a0=0.f,a1=0.f,a2=0.f,a3=0.f;
        #pragma unroll
        for(int jb=0;jb<8;jb++){
            int j = jb*256 + t;
            float4 tv = ef[(size_t)i*NND + j];
            float tt[4] = {tv.x, tv.y, tv.z, tv.w};
            float A[4];
            #pragma unroll
            for(int c=0;c<4;c++){
                float w0 = g_w0[c*NND + j];
                A[c] = tt[c] > 0.f ? fmaf(tt[c], il0v[c], u0v[c]*w0) : tt[c];
            }
            float P = 1.f;
            #pragma unroll
            for(int h=0;h<4;h++) P *= leaky(s1v[h] + g_s2[h*NND + j]);
            P *= leaky(s1ov + g_s2o[j]);
            float e0 = A[0]*P, e1 = A[1]*P, e2 = A[2]*P, e3 = A[3]*P;
            eo[0u*NNE + (size_t)i*NND + j] = e0;
            eo[1u*NNE + (size_t)i*NND + j] = e1;
            eo[2u*NNE + (size_t)i*NND + j] = e2;
            eo[3u*NNE + (size_t)i*NND + j] = e3;
            a0 += e0; a1 += e1; a2 += e2; a3 += e3;
            colacc[jb][0]+=e0; colacc[jb][1]+=e1; colacc[jb][2]+=e2; colacc[jb][3]+=e3;
        }
        float r0=wred(a0), r1=wred(a1), r2=wred(a2), r3=wred(a3);
        if((t&31)==0){ rp[0][ii][w]=r0; rp[1][ii][w]=r1; rp[2][ii][w]=r2; rp[3][ii][w]=r3; }
    }
    __syncthreads();
    if(t < 16){
        int c = t>>2, ii = t&3;
        float s = 0.f;
        for(int q=0;q<8;q++) s += rp[c][ii][q];
        g_small[OFF_OR + c*NND + i0 + ii] = s;
    }
    #pragma unroll
    for(int jb=0;jb<8;jb++){
        int j = jb*256 + t;
        atomicAdd(&g_small[OFF_OC + 0*NND + j], colacc[jb][0]);
        atomicAdd(&g_small[OFF_OC + 1*NND + j], colacc[jb][1]);
        atomicAdd(&g_small[OFF_OC + 2*NND + j], colacc[jb][2]);
        atomicAdd(&g_small[OFF_OC + 3*NND + j], colacc[jb][3]);
    }
}

// ---------------- out-layer: x2 = sum_c dsn(eo_c) @ Whout (256-wide K chunks) ----------------
__global__ void k_outmm(const float* __restrict__ dout){
    int n0 = blockIdx.x*32;
    int kbase = blockIdx.y*256;
    int t = threadIdx.x;
    __shared__ float asS[32][33];
    __shared__ float woS[32][16];
    __shared__ float uoS[4][32], iloS[4];
    const float* eo = dout + 128;
    if(t < 32){
        #pragma unroll
        for(int c=0;c<4;c++) uoS[c][t] = g_uo[c*NND + n0 + t];
    }
    if(t < 4) iloS[t] = g_ilo[t];
    int bn = t>>3, bm4 = (t&7)*4;
    int na = t>>3, gp = (t&7)*2;
    float acc0 = 0.f, acc1 = 0.f;
    __syncthreads();
    for(int mt=0; mt<8; mt++){
        int m0 = kbase + mt*32;
        ((float*)woS)[t]       = g_Whout[(size_t)m0*16 + t];
        ((float*)woS)[t+256]   = g_Whout[(size_t)m0*16 + t + 256];
        #pragma unroll
        for(int k=0;k<4;k++){
            int m = bm4 + k, mg = m0 + m;
            size_t base = (size_t)(n0+bn)*NND + mg;
            float s = 0.f;
            #pragma unroll
            for(int c=0;c<4;c++){
                float e = eo[(size_t)c*NNE + base];
                float wv = g_wo[c*NND + mg];
                s += e > 0.f ? fmaf(e, iloS[c], uoS[c][bn]*wv) : e;
            }
            asS[bn][m] = s;
        }
        __syncthreads();
        #pragma unroll 8
        for(int m=0;m<32;m++){
            float a = asS[na][m];
            acc0 = fmaf(a, woS[m][gp],   acc0);
            acc1 = fmaf(a, woS[m][gp+1], acc1);
        }
        __syncthreads();
    }
    atomicAdd(&g_small[OFF_X2 + (n0+na)*16 + gp],   acc0);
    atomicAdd(&g_small[OFF_X2 + (n0+na)*16 + gp+1], acc1);
}

// ---------------- bn1 stats ----------------
__global__ void k_bn1stats(){
    int t = threadIdx.x;
    int col = t&15, rg = t>>4;
    float s = 0.f, ss = 0.f;
    for(int r=0;r<128;r++){
        float v = g_small[OFF_X2 + (rg*128 + r)*16 + col];
        s += v; ss += v*v;
    }
    __shared__ float S[16][17], SS[16][17];
    S[rg][col] = s; SS[rg][col] = ss;
    __syncthreads();
    if(t < 16){
        float a = 0.f, b = 0.f;
        for(int q=0;q<16;q++){ a += S[q][t]; b += SS[q][t]; }
        float m = a / (float)NND;
        float var = b / (float)NND - m*m;
        g_mean[t] = m;
        g_rstd[t] = rsqrtf(var + 1e-5f);
    }
}

// ---------------- per-node tail ----------------
__global__ void k_tail1(const float* __restrict__ bn1g, const float* __restrict__ bn1b,
                        const float* __restrict__ bss, const float* __restrict__ bsh,
                        const float* __restrict__ m1w1, const float* __restrict__ m1b1,
                        const float* __restrict__ m1w2, const float* __restrict__ m1b2,
                        const int* __restrict__ gidx, const int* __restrict__ didx){
    int t = threadIdx.x;
    int w = t>>5, l = t&31;
    int n = blockIdx.x*8 + w;
    __shared__ float xsS[8][17], g1S[8][65];
    int di = didx[n];
    if(l < 16){
        float v = g_small[OFF_X2 + n*16 + l];
        float xb = elu1((v - g_mean[l]) * g_rstd[l] * bn1g[l] + bn1b[l]);
        float xs = xb * bss[di*16 + l] + bsh[di*16 + l];
        xsS[w][l] = fmaxf(xs, 0.f);
    }
    __syncwarp();
    float a0 = m1b1[l], a1 = m1b1[l+32];
    #pragma unroll
    for(int k=0;k<16;k++){
        float x = xsS[w][k];
        a0 = fmaf(x, m1w1[k*64 + l],      a0);
        a1 = fmaf(x, m1w1[k*64 + l + 32], a1);
    }
    g1S[w][l]    = fmaxf(a0, 0.f);
    g1S[w][l+32] = fmaxf(a1, 0.f);
    __syncwarp();
    float c0 = m1b2[l], c1 = m1b2[l+32];
    #pragma unroll 8
    for(int k=0;k<64;k++){
        float x = g1S[w][k];
        c0 = fmaf(x, m1w2[k*64 + l],      c0);
        c1 = fmaf(x, m1w2[k*64 + l + 32], c1);
    }
    float ns = c1 * (1.f / (1.f + expf(-c0)));
    atomicAdd(&g_small[OFF_GS + gidx[n]*32 + l], ns);
}

// ---------------- graph-level tail ----------------
__global__ void k_tail2(const float* __restrict__ m2w1, const float* __restrict__ m2b1,
                        const float* __restrict__ m2w2, const float* __restrict__ m2b2,
                        const float* __restrict__ bn2g, const float* __restrict__ bn2b,
                        float* __restrict__ dout){
    int t = threadIdx.x;
    __shared__ float r1S[8][33], r2S[8][17];
    {
        int g = t>>5, j = t&31;
        float v = m2b1[j];
        #pragma unroll
        for(int k=0;k<32;k++)
            v = fmaf(g_small[OFF_GS + g*32 + k], m2w1[k*32 + j], v);
        r1S[g][j] = fmaxf(v, 0.f);
    }
    __syncthreads();
    if(t < 128){
        int g = t>>4, j = t&15;
        float v = m2b2[j];
        #pragma unroll
        for(int k=0;k<32;k++)
            v = fmaf(r1S[g][k], m2w2[k*16 + j], v);
        r2S[g][j] = v;
    }
    __syncthreads();
    if(t < 16){
        float m = 0.f;
        for(int g=0;g<8;g++) m += r2S[g][t];
        m *= 0.125f;
        float var = 0.f;
        for(int g=0;g<8;g++){ float d = r2S[g][t] - m; var += d*d; }
        var *= 0.125f;
        float rs = rsqrtf(var + 1e-5f);
        for(int g=0;g<8;g++)
            dout[g*16 + t] = (r2S[g][t] - m) * rs * bn2g[t] + bn2b[t];
    }
}

// ---------------- launch ----------------
extern "C" void kernel_launch(void* const* d_in, const int* in_sizes, int n_in,
                              void* d_out, int out_size) {
    const float* X      = (const float*)d_in[0];
    const float* ef     = (const float*)d_in[1];
    const float* Wheads = (const float*)d_in[2];
    const float* aheads = (const float*)d_in[3];
    const float* Wout   = (const float*)d_in[4];
    const float* aout   = (const float*)d_in[5];
    const float* bn1g   = (const float*)d_in[6];
    const float* bn1b   = (const float*)d_in[7];
    const float* bss    = (const float*)d_in[8];
    const float* bsh    = (const float*)d_in[9];
    const float* m1w1   = (const float*)d_in[10];
    const float* m1b1   = (const float*)d_in[11];
    const float* m1w2   = (const float*)d_in[12];
    const float* m1b2   = (const float*)d_in[13];
    const float* m2w1   = (const float*)d_in[14];
    const float* m2b1   = (const float*)d_in[15];
    const float* m2w2   = (const float*)d_in[16];
    const float* m2b2   = (const float*)d_in[17];
    const float* bn2g   = (const float*)d_in[18];
    const float* bn2b   = (const float*)d_in[19];
    const int*   gidx   = (const int*)d_in[20];
    const int*   didx   = (const int*)d_in[21];
    float* dout = (float*)d_out;
    (void)in_sizes; (void)n_in; (void)out_size;

    cudaFuncSetAttribute(k_headmm_mma, cudaFuncAttributeMaxDynamicSharedMemorySize, OF_TOT);

    k_zero<<<(SMALL_TOTAL+255)/256, 256>>>();
    k_wh<<<dim3(512,4), 256>>>(X, Wheads, aheads);
    k_whsplit<<<dim3(64,4), 256>>>();
    k_rawA<<<512, 256>>>((const float4*)ef);
    k_params<<<4, 256>>>(0);
    k_headA<<<512, 256>>>((const float4*)ef);
    k_headB<<<dim3(64,8), 256>>>((const float4*)ef);
    k_params<<<16, 256>>>(1);
    k_headmm_mma<<<dim3(64,2), 512, OF_TOT>>>((const float4*)ef);
    k_whout<<<2048, 256>>>(Wout);
    k_s12o<<<8, 256>>>(aout);
    k_outA<<<512, 256>>>((const float4*)ef, dout);
    k_params<<<4, 256>>>(2);
    k_outmm<<<dim3(64,8), 256>>>(dout);
    k_bn1stats<<<1, 256>>>();
    k_tail1<<<256, 256>>>(bn1g, bn1b, bss, bsh, m1w1, m1b1, m1w2, m1b2, gidx, didx);
    k_tail2<<<1, 256>>>(m2w1, m2b1, m2w2, m2b2, bn2g, bn2b, dout);
}

// round 16
// speedup vs baseline: 1.1742x; 1.0541x over previous
#include <cuda_runtime.h>
#include <cuda_bf16.h>
#include <math.h>
#include <stdint.h>

#define NND 2048
#define NNE (NND*NND)

// ---------------- device scratch ----------------
__device__ float g_Wh[4*NND*64];
__device__ unsigned short g_WhTh[4*64*NND], g_WhTl[4*64*NND];
__device__ float g_s1[4*NND], g_s2[4*NND];
__device__ float g_Whout[NND*16];
__device__ float g_s1o[NND], g_s2o[NND];
__device__ float g_hpA[NND*1024], g_hpB[NND*1024];
__device__ float g_u0[4*NND], g_w0[4*NND], g_il0[4];
__device__ float g_uh[16*NND], g_wh2[16*NND], g_ilh[16];
__device__ float g_uo[4*NND], g_wo[4*NND], g_ilo[4];
__device__ float g_mean[16], g_rstd[16];

#define OFF_RC0 0
#define OFF_RR0 (4*NND)
#define OFF_HC  (8*NND)
#define OFF_HR  (24*NND)
#define OFF_OC  (40*NND)
#define OFF_OR  (44*NND)
#define OFF_GS  (48*NND)
#define OFF_X2  (48*NND+256)
#define SMALL_TOTAL (48*NND+256+NND*16)
__device__ float g_small[SMALL_TOTAL];

__device__ __forceinline__ float wred(float v){
    v += __shfl_down_sync(0xffffffffu, v, 16);
    v += __shfl_down_sync(0xffffffffu, v, 8);
    v += __shfl_down_sync(0xffffffffu, v, 4);
    v += __shfl_down_sync(0xffffffffu, v, 2);
    v += __shfl_down_sync(0xffffffffu, v, 1);
    return v;
}
__device__ __forceinline__ float leaky(float x){ return x > 0.f ? x : 0.2f*x; }
__device__ __forceinline__ float elu1(float x){ return x > 0.f ? x : (expf(x)-1.f); }
__device__ __forceinline__ unsigned short bfh(float x){ return __bfloat16_as_ushort(__float2bfloat16(x)); }
__device__ __forceinline__ float bff(unsigned short u){ return __bfloat162float(__ushort_as_bfloat16(u)); }
// packed: d = {hi16 = cvt(a), lo16 = cvt(b)}
__device__ __forceinline__ uint32_t cvt2(float a, float b){
    uint32_t r; asm("cvt.rn.bf16x2.f32 %0, %1, %2;" : "=r"(r) : "f"(a), "f"(b)); return r;
}

__device__ __forceinline__ uint32_t smem_u32(const void* p){
    uint32_t a; asm("{ .reg .u64 t; cvta.to.shared.u64 t, %1; cvt.u32.u64 %0, t; }" : "=r"(a) : "l"(p)); return a;
}
__device__ __forceinline__ void ldmx4(uint32_t* r, uint32_t addr){
    asm volatile("ldmatrix.sync.aligned.m8n8.x4.shared.b16 {%0,%1,%2,%3},[%4];"
        : "=r"(r[0]),"=r"(r[1]),"=r"(r[2]),"=r"(r[3]) : "r"(addr));
}
__device__ __forceinline__ void mmabf(float* d, const uint32_t* a, const uint32_t* b){
    asm volatile("mma.sync.aligned.m16n8k16.row.col.f32.bf16.bf16.f32 "
        "{%0,%1,%2,%3},{%4,%5,%6,%7},{%8,%9},{%0,%1,%2,%3};"
        : "+f"(d[0]),"+f"(d[1]),"+f"(d[2]),"+f"(d[3])
        : "r"(a[0]),"r"(a[1]),"r"(a[2]),"r"(a[3]),"r"(b[0]),"r"(b[1]));
}

// smem layout for headmm (bytes). att row stride 80B (32 bf16 + 8 pad).
#define OF_AH 0
#define OF_AL 40960
#define OF_B  81920
#define OF_W  122880
#define OF_S2 124928
#define OF_W0 125440
#define OF_U  125952
#define OF_IL 128000
#define OF_TOT 128064

// ---------------- zero ----------------
__global__ void k_zero(){
    int i = blockIdx.x*256 + threadIdx.x;
    if(i < SMALL_TOTAL) g_small[i] = 0.f;
}

// ---------------- Wh = X @ W_heads[h] (+ fused s1/s2) ----------------
__global__ void k_wh(const float* __restrict__ X, const float* __restrict__ W,
                     const float* __restrict__ ah){
    int h = blockIdx.y;
    int nb = blockIdx.x*4;
    int t = threadIdx.x;
    __shared__ float Xs[4][128];
    __shared__ float aS[4][64];
    #pragma unroll
    for(int q=0;q<2;q++){
        int idx = t + q*256;
        Xs[idx>>7][idx&127] = X[(size_t)(nb + (idx>>7))*128 + (idx&127)];
    }
    __syncthreads();
    int nl = t>>6, f = t&63;
    float a = 0.f;
    #pragma unroll 16
    for(int k=0;k<128;k++)
        a = fmaf(Xs[nl][k], W[((size_t)h*128 + k)*64 + f], a);
    g_Wh[((size_t)h*NND + nb + nl)*64 + f] = a;
    aS[nl][f] = a;
    __syncthreads();
    int w = t>>5, l = t&31;
    if(w < 4){
        float v0 = aS[w][l], v1 = aS[w][l+32];
        float s1 = fmaf(v0, ah[h*128 + l],      v1*ah[h*128 + l + 32]);
        float s2 = fmaf(v0, ah[h*128 + 64 + l], v1*ah[h*128 + 96 + l]);
        s1 = wred(s1); s2 = wred(s2);
        if(l == 0){
            g_s1[h*NND + nb + w] = s1;
            g_s2[h*NND + nb + w] = s2;
        }
    }
}

// ---------------- WhT hi/lo split (smem transpose) ----------------
__global__ void k_whsplit(){
    int h = blockIdx.y;
    int m0 = blockIdx.x*32;
    __shared__ float tile[32][65];
    int t = threadIdx.x;
    #pragma unroll
    for(int q=0;q<8;q++){
        int idx = t + q*256;
        tile[idx>>6][idx&63] = g_Wh[((size_t)h*NND + m0 + (idx>>6))*64 + (idx&63)];
    }
    __syncthreads();
    #pragma unroll
    for(int q=0;q<8;q++){
        int idx = t + q*256;
        int f = idx>>5, m = idx&31;
        float v = tile[m][f];
        unsigned short hi = bfh(v);
        g_WhTh[(size_t)(h*64+f)*NND + m0 + m] = hi;
        g_WhTl[(size_t)(h*64+f)*NND + m0 + m] = bfh(v - bff(hi));
    }
}

// ---------------- raw ef sums: rows + cols fused (deferred wred) ----------------
__global__ void k_rawA(const float4* __restrict__ ef){
    __shared__ float rp[4][4][9];
    int t = threadIdx.x, w = t>>5;
    int i0 = blockIdx.x*4;
    float colacc[8][4];
    float racc[4][4];
    #pragma unroll
    for(int jb=0;jb<8;jb++)
        #pragma unroll
        for(int c=0;c<4;c++) colacc[jb][c] = 0.f;
    #pragma unroll
    for(int ii=0;ii<4;ii++)
        #pragma unroll
        for(int c=0;c<4;c++) racc[ii][c] = 0.f;
    #pragma unroll
    for(int ii=0; ii<4; ii++){
        int i = i0 + ii;
        #pragma unroll
        for(int jb=0;jb<8;jb++){
            float4 v = ef[(size_t)i*NND + jb*256 + t];
            racc[ii][0]+=v.x; racc[ii][1]+=v.y; racc[ii][2]+=v.z; racc[ii][3]+=v.w;
            colacc[jb][0]+=v.x; colacc[jb][1]+=v.y; colacc[jb][2]+=v.z; colacc[jb][3]+=v.w;
        }
    }
    #pragma unroll
    for(int ii=0; ii<4; ii++){
        float r0=wred(racc[ii][0]), r1=wred(racc[ii][1]), r2=wred(racc[ii][2]), r3=wred(racc[ii][3]);
        if((t&31)==0){ rp[0][ii][w]=r0; rp[1][ii][w]=r1; rp[2][ii][w]=r2; rp[3][ii][w]=r3; }
    }
    __syncthreads();
    if(t < 16){
        int c = t>>2, ii = t&3;
        float s = 0.f;
        for(int q=0;q<8;q++) s += rp[c][ii][q];
        g_small[OFF_RR0 + c*NND + i0 + ii] = s;
    }
    #pragma unroll
    for(int jb=0;jb<8;jb++){
        int j = jb*256 + t;
        atomicAdd(&g_small[OFF_RC0 + 0*NND + j], colacc[jb][0]);
        atomicAdd(&g_small[OFF_RC0 + 1*NND + j], colacc[jb][1]);
        atomicAdd(&g_small[OFF_RC0 + 2*NND + j], colacc[jb][2]);
        atomicAdd(&g_small[OFF_RC0 + 3*NND + j], colacc[jb][3]);
    }
}

// ---------------- dsn params ----------------
__global__ void k_params(int mode){
    int ch = blockIdx.x, t = threadIdx.x;
    const float *rs, *cs; float *u, *w, *il;
    if(mode==0){ rs=g_small+OFF_RR0+ch*NND; cs=g_small+OFF_RC0+ch*NND; u=g_u0+ch*NND; w=g_w0+ch*NND; il=g_il0+ch; }
    else if(mode==1){ rs=g_small+OFF_HR+ch*NND; cs=g_small+OFF_HC+ch*NND; u=g_uh+ch*NND; w=g_wh2+ch*NND; il=g_ilh+ch; }
    else { rs=g_small+OFF_OR+ch*NND; cs=g_small+OFF_OC+ch*NND; u=g_uo+ch*NND; w=g_wo+ch*NND; il=g_ilo+ch; }
    __shared__ float smx[256], ssm[256];
    __shared__ float lamS, irS, ilS;
    float mx = -3.4e38f, sm = 0.f;
    #pragma unroll
    for(int q=0;q<8;q++){
        float a = rs[t + q*256]; mx = fmaxf(mx, a); sm += a;
        float b = cs[t + q*256]; mx = fmaxf(mx, b);
    }
    smx[t] = mx; ssm[t] = sm;
    __syncthreads();
    for(int s=128; s; s>>=1){
        if(t < s){ smx[t] = fmaxf(smx[t], smx[t+s]); ssm[t] += ssm[t+s]; }
        __syncthreads();
    }
    if(t==0){
        float lam = smx[0];
        float r = (float)NND*lam - ssm[0];
        lamS = lam; irS = 1.f/r; ilS = 1.f/lam;
        il[0] = ilS;
    }
    __syncthreads();
    float lam = lamS, ir = irS, ilv = ilS;
    #pragma unroll
    for(int q=0;q<8;q++){
        int i = t + q*256;
        u[i] = (lam - rs[i]) * ir;
        w[i] = (lam - cs[i]) * ilv;
    }
}

// ---------------- head row sums (reads ef, inline dsn0; 4 rows/block) ----------------
__global__ void k_headA(const float4* __restrict__ ef){
    __shared__ float rp[16][4][9];
    int t = threadIdx.x, w = t>>5;
    int i0 = blockIdx.x*4;
    float il0v[4];
    #pragma unroll
    for(int c=0;c<4;c++) il0v[c] = g_il0[c];
    for(int ii=0; ii<4; ii++){
        int i = i0 + ii;
        float s1v[4], u0v[4];
        #pragma unroll
        for(int h=0;h<4;h++) s1v[h] = g_s1[h*NND + i];
        #pragma unroll
        for(int c=0;c<4;c++) u0v[c] = g_u0[c*NND + i];
        float acc[16];
        #pragma unroll
        for(int k=0;k<16;k++) acc[k] = 0.f;
        #pragma unroll 2
        for(int jb=0;jb<8;jb++){
            int j = jb*256 + t;
            float4 tv = ef[(size_t)i*NND + j];
            float tt[4] = {tv.x, tv.y, tv.z, tv.w};
            float A[4];
            #pragma unroll
            for(int c=0;c<4;c++){
                float w0 = g_w0[c*NND + j];
                A[c] = tt[c] > 0.f ? fmaf(tt[c], il0v[c], u0v[c]*w0) : tt[c];
            }
            float P = 1.f;
            #pragma unroll
            for(int h=0;h<4;h++){
                P *= leaky(s1v[h] + g_s2[h*NND + j]);
                #pragma unroll
                for(int c=0;c<4;c++) acc[h*4+c] += A[c]*P;
            }
        }
        #pragma unroll
        for(int k=0;k<16;k++){
            float r = wred(acc[k]);
            if((t&31)==0) rp[k][ii][w] = r;
        }
    }
    __syncthreads();
    if(t < 64){
        int k = t>>2, ii = t&3;
        float s = 0.f;
        for(int q=0;q<8;q++) s += rp[k][ii][q];
        g_small[OFF_HR + k*NND + i0 + ii] = s;
    }
}

// ---------------- head col sums (reads ef, inline dsn0; 256-row chunks) ----------------
__global__ void k_headB(const float4* __restrict__ ef){
    __shared__ float cs[8][16][33];
    int t = threadIdx.x;
    int jl = t&31, ig = t>>5;
    int j = blockIdx.x*32 + jl;
    int ibase = blockIdx.y*256 + ig*32;
    float s2v[4], w0v[4], il0v[4];
    #pragma unroll
    for(int h=0;h<4;h++) s2v[h] = g_s2[h*NND + j];
    #pragma unroll
    for(int c=0;c<4;c++){ w0v[c] = g_w0[c*NND + j]; il0v[c] = g_il0[c]; }
    float acc[16];
    #pragma unroll
    for(int k=0;k<16;k++) acc[k] = 0.f;
    for(int r=0;r<32;r++){
        int i = ibase + r;
        float4 tv = ef[(size_t)i*NND + j];
        float tt[4] = {tv.x, tv.y, tv.z, tv.w};
        float A[4];
        #pragma unroll
        for(int c=0;c<4;c++){
            float u0 = g_u0[c*NND + i];
            A[c] = tt[c] > 0.f ? fmaf(tt[c], il0v[c], u0*w0v[c]) : tt[c];
        }
        float P = 1.f;
        #pragma unroll
        for(int h=0;h<4;h++){
            P *= leaky(g_s1[h*NND + i] + s2v[h]);
            #pragma unroll
            for(int c=0;c<4;c++) acc[h*4+c] += A[c]*P;
        }
    }
    #pragma unroll
    for(int k=0;k<16;k++) cs[ig][k][jl] = acc[k];
    __syncthreads();
    #pragma unroll
    for(int q=0;q<2;q++){
        int idx = t + q*256;
        int k = idx>>5, jj = idx&31;
        float s = 0.f;
        for(int g=0;g<8;g++) s += cs[g][k][jj];
        atomicAdd(&g_small[OFF_HC + k*NND + blockIdx.x*32 + jj], s);
    }
}

// ---------------- attention @ Wh, all 4 heads per ef read ----------------
__global__ void __launch_bounds__(512,1) k_headmm_mma(const float4* __restrict__ ef){
    extern __shared__ char sm[];
    int t = threadIdx.x;
    int n0g = blockIdx.x*32;
    int khalf = blockIdx.y;
    uint32_t sb = smem_u32(sm);

    float* wS  = (float*)(sm + OF_W);
    float* s2S = (float*)(sm + OF_S2);
    float* w0S = (float*)(sm + OF_W0);
    float* uS  = (float*)(sm + OF_U);
    float* ilS = (float*)(sm + OF_IL);

    if(t < 512){
        int combo = t>>5, n = t&31;
        uS[combo*32 + n] = g_uh[combo*NND + n0g + n];
    }
    if(t < 16) ilS[t] = g_ilh[t];

    int bn = t>>4;
    int bm = (t&15)*2;
    float s1v[4], u0v[4], il0v[4];
    #pragma unroll
    for(int mh=0; mh<4; mh++) s1v[mh] = g_s1[mh*NND + n0g + bn];
    #pragma unroll
    for(int c=0; c<4; c++){ u0v[c] = g_u0[c*NND + n0g + bn]; il0v[c] = g_il0[c]; }

    float acc[2][8][4];
    #pragma unroll
    for(int a=0;a<2;a++)
        #pragma unroll
        for(int b=0;b<8;b++)
            #pragma unroll
            for(int q=0;q<4;q++) acc[a][b][q] = 0.f;

    int wI = t>>5, l = t&31;
    int wh = wI>>2, wc = wI&3;
    int lr = l&15, lc = l>>4;
    uint32_t aBaseH = sb + OF_AH + wI*2560;
    uint32_t aBaseL = sb + OF_AL + wI*2560;
    uint32_t bBaseH = sb + OF_B + (wh*2+0)*5120;
    uint32_t bBaseL = sb + OF_B + (wh*2+1)*5120;
    uint32_t bf = (uint32_t)((l&7) + ((l>>4)<<3));

    for(int ck=0; ck<32; ck++){
        int m0 = khalf*1024 + ck*32;
        __syncthreads();
        wS[t&511] = g_wh2[(t>>5)*NND + m0 + (t&31)];
        if(t < 128){
            s2S[t] = g_s2[(t>>5)*NND + m0 + (t&31)];
            w0S[t] = g_w0[(t>>5)*NND + m0 + (t&31)];
        }
        if(t < 256){
            int h = t>>6, f = t&63;
            const uint4* ph = (const uint4*)&g_WhTh[(size_t)(h*64+f)*NND + m0];
            const uint4* pl = (const uint4*)&g_WhTl[(size_t)(h*64+f)*NND + m0];
            uint4* dh = (uint4*)(sm + OF_B + (h*2+0)*5120 + f*80);
            uint4* dl = (uint4*)(sm + OF_B + (h*2+1)*5120 + f*80);
            dh[0]=ph[0]; dh[1]=ph[1]; dh[2]=ph[2]; dh[3]=ph[3];
            dl[0]=pl[0]; dl[1]=pl[1]; dl[2]=pl[2]; dl[3]=pl[3];
        }
        __syncthreads();
        {
            const float4* ap = ef + (size_t)(n0g+bn)*NND + m0 + bm;
            float4 Ta = ap[0], Tb = ap[1];
            float Tav[4] = {Ta.x, Ta.y, Ta.z, Ta.w};
            float Tbv[4] = {Tb.x, Tb.y, Tb.z, Tb.w};
            float Aav[4], Abv[4];
            #pragma unroll
            for(int c=0;c<4;c++){
                Aav[c] = Tav[c] > 0.f ? fmaf(Tav[c], il0v[c], u0v[c]*w0S[c*32 + bm])     : Tav[c];
                Abv[c] = Tbv[c] > 0.f ? fmaf(Tbv[c], il0v[c], u0v[c]*w0S[c*32 + bm + 1]) : Tbv[c];
            }
            float Pa = 1.f, Pb = 1.f;
            float Pah[4], Pbh[4];
            #pragma unroll
            for(int mh=0; mh<4; mh++){
                Pa *= leaky(s1v[mh] + s2S[mh*32 + bm]);
                Pb *= leaky(s1v[mh] + s2S[mh*32 + bm + 1]);
                Pah[mh] = Pa; Pbh[mh] = Pb;
            }
            uint32_t off = (uint32_t)(bn*80 + bm*2);
            #pragma unroll
            for(int combo=0; combo<16; combo++){
                int h = combo>>2, c = combo&3;
                float il = ilS[combo];
                float uvv = uS[combo*32 + bn];
                float wa = wS[combo*32 + bm], wb = wS[combo*32 + bm + 1];
                float ea = Aav[c]*Pah[h], eb = Abv[c]*Pbh[h];
                float xa = ea > 0.f ? fmaf(ea, il, uvv*wa) : ea;
                float xb = eb > 0.f ? fmaf(eb, il, uvv*wb) : eb;
                uint32_t hw = cvt2(xb, xa);
                float haf = __uint_as_float(hw << 16);
                float hbf = __uint_as_float(hw & 0xFFFF0000u);
                uint32_t lw = cvt2(xb - hbf, xa - haf);
                *(uint32_t*)(sm + OF_AH + combo*2560 + off) = hw;
                *(uint32_t*)(sm + OF_AL + combo*2560 + off) = lw;
            }
        }
        __syncthreads();
        #pragma unroll
        for(int ki=0; ki<2; ki++){
            uint32_t aH[2][4], aL[2][4];
            #pragma unroll
            for(int mi=0; mi<2; mi++){
                uint32_t ro = (uint32_t)((mi*16 + lr)*80 + (ki*16 + lc*8)*2);
                ldmx4(aH[mi], aBaseH + ro);
                ldmx4(aL[mi], aBaseL + ro);
            }
            uint32_t bk = (uint32_t)(ki*16 + ((l>>3)&1)*8);
            #pragma unroll
            for(int np=0; np<4; np++){
                uint32_t bo = (np*16 + bf)*80 + bk*2;
                uint32_t bH[4], bL[4];
                ldmx4(bH, bBaseH + bo);
                ldmx4(bL, bBaseL + bo);
                // reordered: break accumulator RAW chains (reuse distance 4)
                mmabf(acc[0][np*2],   aH[0], bH);
                mmabf(acc[1][np*2],   aH[1], bH);
                mmabf(acc[0][np*2+1], aH[0], bH+2);
                mmabf(acc[1][np*2+1], aH[1], bH+2);
                mmabf(acc[0][np*2],   aL[0], bH);
                mmabf(acc[1][np*2],   aL[1], bH);
                mmabf(acc[0][np*2+1], aL[0], bH+2);
                mmabf(acc[1][np*2+1], aL[1], bH+2);
                mmabf(acc[0][np*2],   aH[0], bL);
                mmabf(acc[1][np*2],   aH[1], bL);
                mmabf(acc[0][np*2+1], aH[0], bL+2);
                mmabf(acc[1][np*2+1], aH[1], bL+2);
            }
        }
    }
    float* hpK = khalf == 0 ? g_hpA : g_hpB;
    #pragma unroll
    for(int mi=0; mi<2; mi++){
        int nr = n0g + mi*16 + (l>>2);
        #pragma unroll
        for(int ni=0; ni<8; ni++){
            int f = ni*8 + (l&3)*2;
            float* dst = &hpK[(size_t)nr*1024 + wh*256 + wc*64 + f];
            *(float2*)dst = make_float2(acc[mi][ni][0], acc[mi][ni][1]);
            *(float2*)(dst + 8*1024) = make_float2(acc[mi][ni][2], acc[mi][ni][3]);
        }
    }
}

// ---------------- Whout = elu(hpA+hpB) @ W_out ----------------
__global__ void k_whout(const float* __restrict__ Wout){
    int n = blockIdx.x;
    int t = threadIdx.x;
    __shared__ float eS[1024];
    __shared__ float part[16][17];
    {
        float4 ha = ((const float4*)(g_hpA + (size_t)n*1024))[t];
        float4 hb = ((const float4*)(g_hpB + (size_t)n*1024))[t];
        eS[t*4+0] = elu1(ha.x + hb.x);
        eS[t*4+1] = elu1(ha.y + hb.y);
        eS[t*4+2] = elu1(ha.z + hb.z);
        eS[t*4+3] = elu1(ha.w + hb.w);
    }
    __syncthreads();
    int g = t&15, kg = t>>4;
    float s = 0.f;
    #pragma unroll 8
    for(int k=0;k<64;k++)
        s = fmaf(eS[kg*64+k], Wout[(size_t)(kg*64+k)*16 + g], s);
    part[kg][g] = s;
    __syncthreads();
    if(t < 16){
        float a = 0.f;
        for(int q=0;q<16;q++) a += part[q][t];
        g_Whout[n*16 + t] = a;
    }
}

__global__ void k_s12o(const float* __restrict__ aout){
    int n = blockIdx.x*256 + threadIdx.x;
    float s1 = 0.f, s2 = 0.f;
    #pragma unroll
    for(int g=0;g<16;g++){
        float v = g_Whout[n*16+g];
        s1 = fmaf(v, aout[g],    s1);
        s2 = fmaf(v, aout[16+g], s2);
    }
    g_s1o[n] = s1; g_s2o[n] = s2;
}

// ---------------- out-layer e: write edge_attr + row/col sums fused (deferred wred) ----------------
__global__ void k_outA(const float4* __restrict__ ef, float* __restrict__ dout){
    __shared__ float rp[4][4][9];
    int t = threadIdx.x, w = t>>5;
    int i0 = blockIdx.x*4;
    float* eo = dout + 128;
    float il0v[4];
    #pragma unroll
    for(int c=0;c<4;c++) il0v[c] = g_il0[c];
    float colacc[8][4];
    float racc[4][4];
    #pragma unroll
    for(int jb=0;jb<8;jb++)
        #pragma unroll
        for(int c=0;c<4;c++) colacc[jb][c] = 0.f;
    #pragma unroll
    for(int ii=0;ii<4;ii++)
        #pragma unroll
        for(int c=0;c<4;c++) racc[ii][c] = 0.f;
    for(int ii=0; ii<4; ii++){
        int i = i0 + ii;
        float s1v[4], u0v[4];
        #pragma unroll
        for(int h=0;h<4;h++) s1v[h] = g_s1[h*NND + i];
        #pragma unroll
        for(int c=0;c<4;c++) u0v[c] = g_u0[c*NND + i];
        float s1ov = g_s1o[i];
        #pragma unroll
        for(int jb=0;jb<8;jb++){
            int j = jb*256 + t;
            float4 tv = ef[(size_t)i*NND + j];
            float tt[4] = {tv.x, tv.y, tv.z, tv.w};
            float A[4];
            #pragma unroll
            for(int c=0;c<4;c++){
                float w0 = g_w0[c*NND + j];
                A[c] = tt[c] > 0.f ? fmaf(tt[c], il0v[c], u0v[c]*w0) : tt[c];
            }
            float P = 1.f;
            #pragma unroll
            for(int h=0;h<4;h++) P *= leaky(s1v[h] + g_s2[h*NND + j]);
            P *= leaky(s1ov + g_s2o[j]);
            float e0 = A[0]*P, e1 = A[1]*P, e2 = A[2]*P, e3 = A[3]*P;
            eo[0u*NNE + (size_t)i*NND + j] = e0;
            eo[1u*NNE + (size_t)i*NND + j] = e1;
            eo[2u*NNE + (size_t)i*NND + j] = e2;
            eo[3u*NNE + (size_t)i*NND + j] = e3;
            racc[ii][0] += e0; racc[ii][1] += e1; racc[ii][2] += e2; racc[ii][3] += e3;
            colacc[jb][0]+=e0; colacc[jb][1]+=e1; colacc[jb][2]+=e2; colacc[jb][3]+=e3;
        }
    }
    #pragma unroll
    for(int ii=0; ii<4; ii++){
        float r0=wred(racc[ii][0]), r1=wred(racc[ii][1]), r2=wred(racc[ii][2]), r3=wred(racc[ii][3]);
        if((t&31)==0){ rp[0][ii][w]=r0; rp[1][ii][w]=r1; rp[2][ii][w]=r2; rp[3][ii][w]=r3; }
    }
    __syncthreads();
    if(t < 16){
        int c = t>>2, ii = t&3;
        float s = 0.f;
        for(int q=0;q<8;q++) s += rp[c][ii][q];
        g_small[OFF_OR + c*NND + i0 + ii] = s;
    }
    #pragma unroll
    for(int jb=0;jb<8;jb++){
        int j = jb*256 + t;
        atomicAdd(&g_small[OFF_OC + 0*NND + j], colacc[jb][0]);
        atomicAdd(&g_small[OFF_OC + 1*NND + j], colacc[jb][1]);
        atomicAdd(&g_small[OFF_OC + 2*NND + j], colacc[jb][2]);
        atomicAdd(&g_small[OFF_OC + 3*NND + j], colacc[jb][3]);
    }
}

// ---------------- out-layer: x2 = sum_c dsn(eo_c) @ Whout ----------------
__global__ void k_outmm(const float* __restrict__ dout){
    int n0 = blockIdx.x*32;
    int kbase = blockIdx.y*256;
    int t = threadIdx.x;
    __shared__ float asS[32][33];
    __shared__ float woS[32][16];
    __shared__ float uoS[4][32], iloS[4];
    const float* eo = dout + 128;
    if(t < 32){
        #pragma unroll
        for(int c=0;c<4;c++) uoS[c][t] = g_uo[c*NND + n0 + t];
    }
    if(t < 4) iloS[t] = g_ilo[t];
    int bn = t>>3, bm4 = (t&7)*4;
    int na = t>>3, gp = (t&7)*2;
    float acc0 = 0.f, acc1 = 0.f;
    __syncthreads();
    for(int mt=0; mt<8; mt++){
        int m0 = kbase + mt*32;
        ((float*)woS)[t]       = g_Whout[(size_t)m0*16 + t];
        ((float*)woS)[t+256]   = g_Whout[(size_t)m0*16 + t + 256];
        #pragma unroll
        for(int k=0;k<4;k++){
            int m = bm4 + k, mg = m0 + m;
            size_t base = (size_t)(n0+bn)*NND + mg;
            float s = 0.f;
            #pragma unroll
            for(int c=0;c<4;c++){
                float e = eo[(size_t)c*NNE + base];
                float wv = g_wo[c*NND + mg];
                s += e > 0.f ? fmaf(e, iloS[c], uoS[c][bn]*wv) : e;
            }
            asS[bn][m] = s;
        }
        __syncthreads();
        #pragma unroll 8
        for(int m=0;m<32;m++){
            float a = asS[na][m];
            acc0 = fmaf(a, woS[m][gp],   acc0);
            acc1 = fmaf(a, woS[m][gp+1], acc1);
        }
        __syncthreads();
    }
    atomicAdd(&g_small[OFF_X2 + (n0+na)*16 + gp],   acc0);
    atomicAdd(&g_small[OFF_X2 + (n0+na)*16 + gp+1], acc1);
}

// ---------------- bn1 stats ----------------
__global__ void k_bn1stats(){
    int t = threadIdx.x;
    int col = t&15, rg = t>>4;
    float s = 0.f, ss = 0.f;
    for(int r=0;r<128;r++){
        float v = g_small[OFF_X2 + (rg*128 + r)*16 + col];
        s += v; ss += v*v;
    }
    __shared__ float S[16][17], SS[16][17];
    S[rg][col] = s; SS[rg][col] = ss;
    __syncthreads();
    if(t < 16){
        float a = 0.f, b = 0.f;
        for(int q=0;q<16;q++){ a += S[q][t]; b += SS[q][t]; }
        float m = a / (float)NND;
        float var = b / (float)NND - m*m;
        g_mean[t] = m;
        g_rstd[t] = rsqrtf(var + 1e-5f);
    }
}

// ---------------- per-node tail ----------------
__global__ void k_tail1(const float* __restrict__ bn1g, const float* __restrict__ bn1b,
                        const float* __restrict__ bss, const float* __restrict__ bsh,
                        const float* __restrict__ m1w1, const float* __restrict__ m1b1,
                        const float* __restrict__ m1w2, const float* __restrict__ m1b2,
                        const int* __restrict__ gidx, const int* __restrict__ didx){
    int t = threadIdx.x;
    int w = t>>5, l = t&31;
    int n = blockIdx.x*8 + w;
    __shared__ float xsS[8][17], g1S[8][65];
    int di = didx[n];
    if(l < 16){
        float v = g_small[OFF_X2 + n*16 + l];
        float xb = elu1((v - g_mean[l]) * g_rstd[l] * bn1g[l] + bn1b[l]);
        float xs = xb * bss[di*16 + l] + bsh[di*16 + l];
        xsS[w][l] = fmaxf(xs, 0.f);
    }
    __syncwarp();
    float a0 = m1b1[l], a1 = m1b1[l+32];
    #pragma unroll
    for(int k=0;k<16;k++){
        float x = xsS[w][k];
        a0 = fmaf(x, m1w1[k*64 + l],      a0);
        a1 = fmaf(x, m1w1[k*64 + l + 32], a1);
    }
    g1S[w][l]    = fmaxf(a0, 0.f);
    g1S[w][l+32] = fmaxf(a1, 0.f);
    __syncwarp();
    float c0 = m1b2[l], c1 = m1b2[l+32];
    #pragma unroll 8
    for(int k=0;k<64;k++){
        float x = g1S[w][k];
        c0 = fmaf(x, m1w2[k*64 + l],      c0);
        c1 = fmaf(x, m1w2[k*64 + l + 32], c1);
    }
    float ns = c1 * (1.f / (1.f + expf(-c0)));
    atomicAdd(&g_small[OFF_GS + gidx[n]*32 + l], ns);
}

// ---------------- graph-level tail ----------------
__global__ void k_tail2(const float* __restrict__ m2w1, const float* __restrict__ m2b1,
                        const float* __restrict__ m2w2, const float* __restrict__ m2b2,
                        const float* __restrict__ bn2g, const float* __restrict__ bn2b,
                        float* __restrict__ dout){
    int t = threadIdx.x;
    __shared__ float r1S[8][33], r2S[8][17];
    {
        int g = t>>5, j = t&31;
        float v = m2b1[j];
        #pragma unroll
        for(int k=0;k<32;k++)
            v = fmaf(g_small[OFF_GS + g*32 + k], m2w1[k*32 + j], v);
        r1S[g][j] = fmaxf(v, 0.f);
    }
    __syncthreads();
    if(t < 128){
        int g = t>>4, j = t&15;
        float v = m2b2[j];
        #pragma unroll
        for(int k=0;k<32;k++)
            v = fmaf(r1S[g][k], m2w2[k*16 + j], v);
        r2S[g][j] = v;
    }
    __syncthreads();
    if(t < 16){
        float m = 0.f;
        for(int g=0;g<8;g++) m += r2S[g][t];
        m *= 0.125f;
        float var = 0.f;
        for(int g=0;g<8;g++){ float d = r2S[g][t] - m; var += d*d; }
        var *= 0.125f;
        float rs = rsqrtf(var + 1e-5f);
        for(int g=0;g<8;g++)
            dout[g*16 + t] = (r2S[g][t] - m) * rs * bn2g[t] + bn2b[t];
    }
}

// ---------------- launch ----------------
extern "C" void kernel_launch(void* const* d_in, const int* in_sizes, int n_in,
                              void* d_out, int out_size) {
    const float* X      = (const float*)d_in[0];
    const float* ef     = (const float*)d_in[1];
    const float* Wheads = (const float*)d_in[2];
    const float* aheads = (const float*)d_in[3];
    const float* Wout   = (const float*)d_in[4];
    const float* aout   = (const float*)d_in[5];
    const float* bn1g   = (const float*)d_in[6];
    const float* bn1b   = (const float*)d_in[7];
    const float* bss    = (const float*)d_in[8];
    const float* bsh    = (const float*)d_in[9];
    const float* m1w1   = (const float*)d_in[10];
    const float* m1b1   = (const float*)d_in[11];
    const float* m1w2   = (const float*)d_in[12];
    const float* m1b2   = (const float*)d_in[13];
    const float* m2w1   = (const float*)d_in[14];
    const float* m2b1   = (const float*)d_in[15];
    const float* m2w2   = (const float*)d_in[16];
    const float* m2b2   = (const float*)d_in[17];
    const float* bn2g   = (const float*)d_in[18];
    const float* bn2b   = (const float*)d_in[19];
    const int*   gidx   = (const int*)d_in[20];
    const int*   didx   = (const int*)d_in[21];
    float* dout = (float*)d_out;
    (void)in_sizes; (void)n_in; (void)out_size;

    cudaFuncSetAttribute(k_headmm_mma, cudaFuncAttributeMaxDynamicSharedMemorySize, OF_TOT);

    k_zero<<<(SMALL_TOTAL+255)/256, 256>>>();
    k_wh<<<dim3(512,4), 256>>>(X, Wheads, aheads);
    k_whsplit<<<dim3(64,4), 256>>>();
    k_rawA<<<512, 256>>>((const float4*)ef);
    k_params<<<4, 256>>>(0);
    k_headA<<<512, 256>>>((const float4*)ef);
    k_headB<<<dim3(64,8), 256>>>((const float4*)ef);
    k_params<<<16, 256>>>(1);
    k_headmm_mma<<<dim3(64,2), 512, OF_TOT>>>((const float4*)ef);
    k_whout<<<2048, 256>>>(Wout);
    k_s12o<<<8, 256>>>(aout);
    k_outA<<<512, 256>>>((const float4*)ef, dout);
    k_params<<<4, 256>>>(2);
    k_outmm<<<dim3(64,8), 256>>>(dout);
    k_bn1stats<<<1, 256>>>();
    k_tail1<<<256, 256>>>(bn1g, bn1b, bss, bsh, m1w1, m1b1, m1w2, m1b2, gidx, didx);
    k_tail2<<<1, 256>>>(m2w1, m2b1, m2w2, m2b2, bn2g, bn2b, dout);
}

// round 17
// speedup vs baseline: 1.1999x; 1.0219x over previous
#include <cuda_runtime.h>
#include <cuda_bf16.h>
#include <math.h>
#include <stdint.h>

#define NND 2048
#define NNE (NND*NND)

// ---------------- device scratch ----------------
__device__ float g_Wh[4*NND*64];
__device__ unsigned short g_WhTh[4*64*NND], g_WhTl[4*64*NND];
__device__ float g_s1[4*NND], g_s2[4*NND];
__device__ float g_Whout[NND*16];
__device__ float g_s1o[NND], g_s2o[NND];
__device__ float g_hpA[NND*1024], g_hpB[NND*1024];
__device__ float g_u0[4*NND], g_w0[4*NND], g_il0[4];
__device__ float g_uh[16*NND], g_wh2[16*NND], g_ilh[16];
__device__ float g_uo[4*NND], g_wo[4*NND], g_ilo[4];
__device__ float g_mean[16], g_rstd[16];

#define OFF_RC0 0
#define OFF_RR0 (4*NND)
#define OFF_HC  (8*NND)
#define OFF_HR  (24*NND)
#define OFF_OC  (40*NND)
#define OFF_OR  (44*NND)
#define OFF_GS  (48*NND)
#define OFF_X2  (48*NND+256)
#define SMALL_TOTAL (48*NND+256+NND*16)
__device__ float g_small[SMALL_TOTAL];

__device__ __forceinline__ float wred(float v){
    v += __shfl_down_sync(0xffffffffu, v, 16);
    v += __shfl_down_sync(0xffffffffu, v, 8);
    v += __shfl_down_sync(0xffffffffu, v, 4);
    v += __shfl_down_sync(0xffffffffu, v, 2);
    v += __shfl_down_sync(0xffffffffu, v, 1);
    return v;
}
__device__ __forceinline__ float leaky(float x){ return x > 0.f ? x : 0.2f*x; }
__device__ __forceinline__ float elu1(float x){ return x > 0.f ? x : (expf(x)-1.f); }
__device__ __forceinline__ unsigned short bfh(float x){ return __bfloat16_as_ushort(__float2bfloat16(x)); }
__device__ __forceinline__ float bff(unsigned short u){ return __bfloat162float(__ushort_as_bfloat16(u)); }
__device__ __forceinline__ uint32_t cvt2(float a, float b){
    uint32_t r; asm("cvt.rn.bf16x2.f32 %0, %1, %2;" : "=r"(r) : "f"(a), "f"(b)); return r;
}

__device__ __forceinline__ uint32_t smem_u32(const void* p){
    uint32_t a; asm("{ .reg .u64 t; cvta.to.shared.u64 t, %1; cvt.u32.u64 %0, t; }" : "=r"(a) : "l"(p)); return a;
}
__device__ __forceinline__ void ldmx4(uint32_t* r, uint32_t addr){
    asm volatile("ldmatrix.sync.aligned.m8n8.x4.shared.b16 {%0,%1,%2,%3},[%4];"
        : "=r"(r[0]),"=r"(r[1]),"=r"(r[2]),"=r"(r[3]) : "r"(addr));
}
__device__ __forceinline__ void mmabf(float* d, const uint32_t* a, const uint32_t* b){
    asm volatile("mma.sync.aligned.m16n8k16.row.col.f32.bf16.bf16.f32 "
        "{%0,%1,%2,%3},{%4,%5,%6,%7},{%8,%9},{%0,%1,%2,%3};"
        : "+f"(d[0]),"+f"(d[1]),"+f"(d[2]),"+f"(d[3])
        : "r"(a[0]),"r"(a[1]),"r"(a[2]),"r"(a[3]),"r"(b[0]),"r"(b[1]));
}

// smem layout for headmm (bytes). att row stride 80B (32 bf16 + 8 pad).
#define OF_AH 0
#define OF_AL 40960
#define OF_B  81920
#define OF_W  122880
#define OF_S2 124928
#define OF_W0 125440
#define OF_U  125952
#define OF_IL 128000
#define OF_TOT 128064

// ---------------- zero ----------------
__global__ void k_zero(){
    int i = blockIdx.x*256 + threadIdx.x;
    if(i < SMALL_TOTAL) g_small[i] = 0.f;
}

// ---------------- Wh = X @ W_heads[h] (+ fused s1/s2) ----------------
__global__ void k_wh(const float* __restrict__ X, const float* __restrict__ W,
                     const float* __restrict__ ah){
    int h = blockIdx.y;
    int nb = blockIdx.x*4;
    int t = threadIdx.x;
    __shared__ float Xs[4][128];
    __shared__ float aS[4][64];
    #pragma unroll
    for(int q=0;q<2;q++){
        int idx = t + q*256;
        Xs[idx>>7][idx&127] = X[(size_t)(nb + (idx>>7))*128 + (idx&127)];
    }
    __syncthreads();
    int nl = t>>6, f = t&63;
    float a = 0.f;
    #pragma unroll 16
    for(int k=0;k<128;k++)
        a = fmaf(Xs[nl][k], W[((size_t)h*128 + k)*64 + f], a);
    g_Wh[((size_t)h*NND + nb + nl)*64 + f] = a;
    aS[nl][f] = a;
    __syncthreads();
    int w = t>>5, l = t&31;
    if(w < 4){
        float v0 = aS[w][l], v1 = aS[w][l+32];
        float s1 = fmaf(v0, ah[h*128 + l],      v1*ah[h*128 + l + 32]);
        float s2 = fmaf(v0, ah[h*128 + 64 + l], v1*ah[h*128 + 96 + l]);
        s1 = wred(s1); s2 = wred(s2);
        if(l == 0){
            g_s1[h*NND + nb + w] = s1;
            g_s2[h*NND + nb + w] = s2;
        }
    }
}

// ---------------- WhT hi/lo split (smem transpose) ----------------
__global__ void k_whsplit(){
    int h = blockIdx.y;
    int m0 = blockIdx.x*32;
    __shared__ float tile[32][65];
    int t = threadIdx.x;
    #pragma unroll
    for(int q=0;q<8;q++){
        int idx = t + q*256;
        tile[idx>>6][idx&63] = g_Wh[((size_t)h*NND + m0 + (idx>>6))*64 + (idx&63)];
    }
    __syncthreads();
    #pragma unroll
    for(int q=0;q<8;q++){
        int idx = t + q*256;
        int f = idx>>5, m = idx&31;
        float v = tile[m][f];
        unsigned short hi = bfh(v);
        g_WhTh[(size_t)(h*64+f)*NND + m0 + m] = hi;
        g_WhTl[(size_t)(h*64+f)*NND + m0 + m] = bfh(v - bff(hi));
    }
}

// ---------------- raw ef sums: rows + cols fused (immediate wred, R15 form) ----------------
__global__ void k_rawA(const float4* __restrict__ ef){
    __shared__ float rp[4][4][9];
    int t = threadIdx.x, w = t>>5;
    int i0 = blockIdx.x*4;
    float colacc[8][4];
    #pragma unroll
    for(int jb=0;jb<8;jb++)
        #pragma unroll
        for(int c=0;c<4;c++) colacc[jb][c] = 0.f;
    for(int ii=0; ii<4; ii++){
        int i = i0 + ii;
        float a0=0.f,a1=0.f,a2=0.f,a3=0.f;
        #pragma unroll
        for(int jb=0;jb<8;jb++){
            float4 v = ef[(size_t)i*NND + jb*256 + t];
            a0+=v.x; a1+=v.y; a2+=v.z; a3+=v.w;
            colacc[jb][0]+=v.x; colacc[jb][1]+=v.y; colacc[jb][2]+=v.z; colacc[jb][3]+=v.w;
        }
        float r0=wred(a0), r1=wred(a1), r2=wred(a2), r3=wred(a3);
        if((t&31)==0){ rp[0][ii][w]=r0; rp[1][ii][w]=r1; rp[2][ii][w]=r2; rp[3][ii][w]=r3; }
    }
    __syncthreads();
    if(t < 16){
        int c = t>>2, ii = t&3;
        float s = 0.f;
        for(int q=0;q<8;q++) s += rp[c][ii][q];
        g_small[OFF_RR0 + c*NND + i0 + ii] = s;
    }
    #pragma unroll
    for(int jb=0;jb<8;jb++){
        int j = jb*256 + t;
        atomicAdd(&g_small[OFF_RC0 + 0*NND + j], colacc[jb][0]);
        atomicAdd(&g_small[OFF_RC0 + 1*NND + j], colacc[jb][1]);
        atomicAdd(&g_small[OFF_RC0 + 2*NND + j], colacc[jb][2]);
        atomicAdd(&g_small[OFF_RC0 + 3*NND + j], colacc[jb][3]);
    }
}

// ---------------- dsn params ----------------
__global__ void k_params(int mode){
    int ch = blockIdx.x, t = threadIdx.x;
    const float *rs, *cs; float *u, *w, *il;
    if(mode==0){ rs=g_small+OFF_RR0+ch*NND; cs=g_small+OFF_RC0+ch*NND; u=g_u0+ch*NND; w=g_w0+ch*NND; il=g_il0+ch; }
    else if(mode==1){ rs=g_small+OFF_HR+ch*NND; cs=g_small+OFF_HC+ch*NND; u=g_uh+ch*NND; w=g_wh2+ch*NND; il=g_ilh+ch; }
    else { rs=g_small+OFF_OR+ch*NND; cs=g_small+OFF_OC+ch*NND; u=g_uo+ch*NND; w=g_wo+ch*NND; il=g_ilo+ch; }
    __shared__ float smx[256], ssm[256];
    __shared__ float lamS, irS, ilS;
    float mx = -3.4e38f, sm = 0.f;
    #pragma unroll
    for(int q=0;q<8;q++){
        float a = rs[t + q*256]; mx = fmaxf(mx, a); sm += a;
        float b = cs[t + q*256]; mx = fmaxf(mx, b);
    }
    smx[t] = mx; ssm[t] = sm;
    __syncthreads();
    for(int s=128; s; s>>=1){
        if(t < s){ smx[t] = fmaxf(smx[t], smx[t+s]); ssm[t] += ssm[t+s]; }
        __syncthreads();
    }
    if(t==0){
        float lam = smx[0];
        float r = (float)NND*lam - ssm[0];
        lamS = lam; irS = 1.f/r; ilS = 1.f/lam;
        il[0] = ilS;
    }
    __syncthreads();
    float lam = lamS, ir = irS, ilv = ilS;
    #pragma unroll
    for(int q=0;q<8;q++){
        int i = t + q*256;
        u[i] = (lam - rs[i]) * ir;
        w[i] = (lam - cs[i]) * ilv;
    }
}

// ---------------- FUSED head row+col sums: one ef pass ----------------
__global__ void __launch_bounds__(256) k_headAB(const float4* __restrict__ ef){
    __shared__ float rp[16][4][9];
    int t = threadIdx.x, w = t>>5;
    int i0 = blockIdx.x*4;
    float il0v[4];
    #pragma unroll
    for(int c=0;c<4;c++) il0v[c] = g_il0[c];
    float s1v[4][4], u0v[4][4];
    #pragma unroll
    for(int ii=0;ii<4;ii++){
        #pragma unroll
        for(int h=0;h<4;h++) s1v[ii][h] = g_s1[h*NND + i0 + ii];
        #pragma unroll
        for(int c=0;c<4;c++) u0v[ii][c] = g_u0[c*NND + i0 + ii];
    }
    float racc[4][16];
    #pragma unroll
    for(int ii=0;ii<4;ii++)
        #pragma unroll
        for(int k=0;k<16;k++) racc[ii][k] = 0.f;
    #pragma unroll 1
    for(int jb=0; jb<8; jb++){
        int j = jb*256 + t;
        float w0j[4], s2j[4];
        #pragma unroll
        for(int c=0;c<4;c++) w0j[c] = g_w0[c*NND + j];
        #pragma unroll
        for(int h=0;h<4;h++) s2j[h] = g_s2[h*NND + j];
        float colacc[16];
        #pragma unroll
        for(int k=0;k<16;k++) colacc[k] = 0.f;
        #pragma unroll
        for(int ii=0; ii<4; ii++){
            float4 tv = ef[(size_t)(i0+ii)*NND + j];
            float tt[4] = {tv.x, tv.y, tv.z, tv.w};
            float A[4];
            #pragma unroll
            for(int c=0;c<4;c++)
                A[c] = tt[c] > 0.f ? fmaf(tt[c], il0v[c], u0v[ii][c]*w0j[c]) : tt[c];
            float P = 1.f;
            #pragma unroll
            for(int h=0;h<4;h++){
                P *= leaky(s1v[ii][h] + s2j[h]);
                #pragma unroll
                for(int c=0;c<4;c++){
                    float v = A[c]*P;
                    racc[ii][h*4+c] += v;
                    colacc[h*4+c] += v;
                }
            }
        }
        #pragma unroll
        for(int k=0;k<16;k++)
            atomicAdd(&g_small[OFF_HC + k*NND + j], colacc[k]);
    }
    #pragma unroll
    for(int ii=0; ii<4; ii++)
        #pragma unroll
        for(int k=0;k<16;k++){
            float r = wred(racc[ii][k]);
            if((t&31)==0) rp[k][ii][w] = r;
        }
    __syncthreads();
    if(t < 64){
        int k = t>>2, ii = t&3;
        float s = 0.f;
        for(int q=0;q<8;q++) s += rp[k][ii][q];
        g_small[OFF_HR + k*NND + i0 + ii] = s;
    }
}

// ---------------- attention @ Wh, all 4 heads per ef read ----------------
__global__ void __launch_bounds__(512,1) k_headmm_mma(const float4* __restrict__ ef){
    extern __shared__ char sm[];
    int t = threadIdx.x;
    int n0g = blockIdx.x*32;
    int khalf = blockIdx.y;
    uint32_t sb = smem_u32(sm);

    float* wS  = (float*)(sm + OF_W);
    float* s2S = (float*)(sm + OF_S2);
    float* w0S = (float*)(sm + OF_W0);
    float* uS  = (float*)(sm + OF_U);
    float* ilS = (float*)(sm + OF_IL);

    if(t < 512){
        int combo = t>>5, n = t&31;
        uS[combo*32 + n] = g_uh[combo*NND + n0g + n];
    }
    if(t < 16) ilS[t] = g_ilh[t];

    int bn = t>>4;
    int bm = (t&15)*2;
    float s1v[4], u0v[4], il0v[4];
    #pragma unroll
    for(int mh=0; mh<4; mh++) s1v[mh] = g_s1[mh*NND + n0g + bn];
    #pragma unroll
    for(int c=0; c<4; c++){ u0v[c] = g_u0[c*NND + n0g + bn]; il0v[c] = g_il0[c]; }

    float acc[2][8][4];
    #pragma unroll
    for(int a=0;a<2;a++)
        #pragma unroll
        for(int b=0;b<8;b++)
            #pragma unroll
            for(int q=0;q<4;q++) acc[a][b][q] = 0.f;

    int wI = t>>5, l = t&31;
    int wh = wI>>2, wc = wI&3;
    int lr = l&15, lc = l>>4;
    uint32_t aBaseH = sb + OF_AH + wI*2560;
    uint32_t aBaseL = sb + OF_AL + wI*2560;
    uint32_t bBaseH = sb + OF_B + (wh*2+0)*5120;
    uint32_t bBaseL = sb + OF_B + (wh*2+1)*5120;
    uint32_t bf = (uint32_t)((l&7) + ((l>>4)<<3));

    for(int ck=0; ck<32; ck++){
        int m0 = khalf*1024 + ck*32;
        // prefetch ef tile before barriers so latency overlaps staging
        const float4* ap = ef + (size_t)(n0g+bn)*NND + m0 + bm;
        float4 Ta = ap[0], Tb = ap[1];
        __syncthreads();
        wS[t&511] = g_wh2[(t>>5)*NND + m0 + (t&31)];
        if(t < 128){
            s2S[t] = g_s2[(t>>5)*NND + m0 + (t&31)];
            w0S[t] = g_w0[(t>>5)*NND + m0 + (t&31)];
        }
        if(t < 256){
            int h = t>>6, f = t&63;
            const uint4* ph = (const uint4*)&g_WhTh[(size_t)(h*64+f)*NND + m0];
            const uint4* pl = (const uint4*)&g_WhTl[(size_t)(h*64+f)*NND + m0];
            uint4* dh = (uint4*)(sm + OF_B + (h*2+0)*5120 + f*80);
            uint4* dl = (uint4*)(sm + OF_B + (h*2+1)*5120 + f*80);
            dh[0]=ph[0]; dh[1]=ph[1]; dh[2]=ph[2]; dh[3]=ph[3];
            dl[0]=pl[0]; dl[1]=pl[1]; dl[2]=pl[2]; dl[3]=pl[3];
        }
        __syncthreads();
        {
            float Tav[4] = {Ta.x, Ta.y, Ta.z, Ta.w};
            float Tbv[4] = {Tb.x, Tb.y, Tb.z, Tb.w};
            float Aav[4], Abv[4];
            #pragma unroll
            for(int c=0;c<4;c++){
                Aav[c] = Tav[c] > 0.f ? fmaf(Tav[c], il0v[c], u0v[c]*w0S[c*32 + bm])     : Tav[c];
                Abv[c] = Tbv[c] > 0.f ? fmaf(Tbv[c], il0v[c], u0v[c]*w0S[c*32 + bm + 1]) : Tbv[c];
            }
            float Pa = 1.f, Pb = 1.f;
            float Pah[4], Pbh[4];
            #pragma unroll
            for(int mh=0; mh<4; mh++){
                Pa *= leaky(s1v[mh] + s2S[mh*32 + bm]);
                Pb *= leaky(s1v[mh] + s2S[mh*32 + bm + 1]);
                Pah[mh] = Pa; Pbh[mh] = Pb;
            }
            uint32_t off = (uint32_t)(bn*80 + bm*2);
            #pragma unroll
            for(int combo=0; combo<16; combo++){
                int h = combo>>2, c = combo&3;
                float il = ilS[combo];
                float uvv = uS[combo*32 + bn];
                float wa = wS[combo*32 + bm], wb = wS[combo*32 + bm + 1];
                float ea = Aav[c]*Pah[h], eb = Abv[c]*Pbh[h];
                float xa = ea > 0.f ? fmaf(ea, il, uvv*wa) : ea;
                float xb = eb > 0.f ? fmaf(eb, il, uvv*wb) : eb;
                uint32_t hw = cvt2(xb, xa);
                float haf = __uint_as_float(hw << 16);
                float hbf = __uint_as_float(hw & 0xFFFF0000u);
                uint32_t lw = cvt2(xb - hbf, xa - haf);
                *(uint32_t*)(sm + OF_AH + combo*2560 + off) = hw;
                *(uint32_t*)(sm + OF_AL + combo*2560 + off) = lw;
            }
        }
        __syncthreads();
        #pragma unroll
        for(int ki=0; ki<2; ki++){
            uint32_t aH[2][4], aL[2][4];
            #pragma unroll
            for(int mi=0; mi<2; mi++){
                uint32_t ro = (uint32_t)((mi*16 + lr)*80 + (ki*16 + lc*8)*2);
                ldmx4(aH[mi], aBaseH + ro);
                ldmx4(aL[mi], aBaseL + ro);
            }
            uint32_t bk = (uint32_t)(ki*16 + ((l>>3)&1)*8);
            #pragma unroll
            for(int np=0; np<4; np++){
                uint32_t bo = (np*16 + bf)*80 + bk*2;
                uint32_t bH[4], bL[4];
                ldmx4(bH, bBaseH + bo);
                ldmx4(bL, bBaseL + bo);
                mmabf(acc[0][np*2],   aH[0], bH);
                mmabf(acc[1][np*2],   aH[1], bH);
                mmabf(acc[0][np*2+1], aH[0], bH+2);
                mmabf(acc[1][np*2+1], aH[1], bH+2);
                mmabf(acc[0][np*2],   aL[0], bH);
                mmabf(acc[1][np*2],   aL[1], bH);
                mmabf(acc[0][np*2+1], aL[0], bH+2);
                mmabf(acc[1][np*2+1], aL[1], bH+2);
                mmabf(acc[0][np*2],   aH[0], bL);
                mmabf(acc[1][np*2],   aH[1], bL);
                mmabf(acc[0][np*2+1], aH[0], bL+2);
                mmabf(acc[1][np*2+1], aH[1], bL+2);
            }
        }
    }
    float* hpK = khalf == 0 ? g_hpA : g_hpB;
    #pragma unroll
    for(int mi=0; mi<2; mi++){
        int nr = n0g + mi*16 + (l>>2);
        #pragma unroll
        for(int ni=0; ni<8; ni++){
            int f = ni*8 + (l&3)*2;
            float* dst = &hpK[(size_t)nr*1024 + wh*256 + wc*64 + f];
            *(float2*)dst = make_float2(acc[mi][ni][0], acc[mi][ni][1]);
            *(float2*)(dst + 8*1024) = make_float2(acc[mi][ni][2], acc[mi][ni][3]);
        }
    }
}

// ---------------- Whout = elu(hpA+hpB) @ W_out ----------------
__global__ void k_whout(const float* __restrict__ Wout){
    int n = blockIdx.x;
    int t = threadIdx.x;
    __shared__ float eS[1024];
    __shared__ float part[16][17];
    {
        float4 ha = ((const float4*)(g_hpA + (size_t)n*1024))[t];
        float4 hb = ((const float4*)(g_hpB + (size_t)n*1024))[t];
        eS[t*4+0] = elu1(ha.x + hb.x);
        eS[t*4+1] = elu1(ha.y + hb.y);
        eS[t*4+2] = elu1(ha.z + hb.z);
        eS[t*4+3] = elu1(ha.w + hb.w);
    }
    __syncthreads();
    int g = t&15, kg = t>>4;
    float s = 0.f;
    #pragma unroll 8
    for(int k=0;k<64;k++)
        s = fmaf(eS[kg*64+k], Wout[(size_t)(kg*64+k)*16 + g], s);
    part[kg][g] = s;
    __syncthreads();
    if(t < 16){
        float a = 0.f;
        for(int q=0;q<16;q++) a += part[q][t];
        g_Whout[n*16 + t] = a;
    }
}

__global__ void k_s12o(const float* __restrict__ aout){
    int n = blockIdx.x*256 + threadIdx.x;
    float s1 = 0.f, s2 = 0.f;
    #pragma unroll
    for(int g=0;g<16;g++){
        float v = g_Whout[n*16+g];
        s1 = fmaf(v, aout[g],    s1);
        s2 = fmaf(v, aout[16+g], s2);
    }
    g_s1o[n] = s1; g_s2o[n] = s2;
}

// ---------------- out-layer e: write edge_attr + row/col sums fused ----------------
__global__ void k_outA(const float4* __restrict__ ef, float* __restrict__ dout){
    __shared__ float rp[4][4][9];
    int t = threadIdx.x, w = t>>5;
    int i0 = blockIdx.x*4;
    float* eo = dout + 128;
    float il0v[4];
    #pragma unroll
    for(int c=0;c<4;c++) il0v[c] = g_il0[c];
    float colacc[8][4];
    float racc[4][4];
    #pragma unroll
    for(int jb=0;jb<8;jb++)
        #pragma unroll
        for(int c=0;c<4;c++) colacc[jb][c] = 0.f;
    #pragma unroll
    for(int ii=0;ii<4;ii++)
        #pragma unroll
        for(int c=0;c<4;c++) racc[ii][c] = 0.f;
    for(int ii=0; ii<4; ii++){
        int i = i0 + ii;
        float s1v[4], u0v[4];
        #pragma unroll
        for(int h=0;h<4;h++) s1v[h] = g_s1[h*NND + i];
        #pragma unroll
        for(int c=0;c<4;c++) u0v[c] = g_u0[c*NND + i];
        float s1ov = g_s1o[i];
        #pragma unroll
        for(int jb=0;jb<8;jb++){
            int j = jb*256 + t;
            float4 tv = ef[(size_t)i*NND + j];
            float tt[4] = {tv.x, tv.y, tv.z, tv.w};
            float A[4];
            #pragma unroll
            for(int c=0;c<4;c++){
                float w0 = g_w0[c*NND + j];
                A[c] = tt[c] > 0.f ? fmaf(tt[c], il0v[c], u0v[c]*w0) : tt[c];
            }
            float P = 1.f;
            #pragma unroll
            for(int h=0;h<4;h++) P *= leaky(s1v[h] + g_s2[h*NND + j]);
            P *= leaky(s1ov + g_s2o[j]);
            float e0 = A[0]*P, e1 = A[1]*P, e2 = A[2]*P, e3 = A[3]*P;
            eo[0u*NNE + (size_t)i*NND + j] = e0;
            eo[1u*NNE + (size_t)i*NND + j] = e1;
            eo[2u*NNE + (size_t)i*NND + j] = e2;
            eo[3u*NNE + (size_t)i*NND + j] = e3;
            racc[ii][0] += e0; racc[ii][1] += e1; racc[ii][2] += e2; racc[ii][3] += e3;
            colacc[jb][0]+=e0; colacc[jb][1]+=e1; colacc[jb][2]+=e2; colacc[jb][3]+=e3;
        }
    }
    #pragma unroll
    for(int ii=0; ii<4; ii++){
        float r0=wred(racc[ii][0]), r1=wred(racc[ii][1]), r2=wred(racc[ii][2]), r3=wred(racc[ii][3]);
        if((t&31)==0){ rp[0][ii][w]=r0; rp[1][ii][w]=r1; rp[2][ii][w]=r2; rp[3][ii][w]=r3; }
    }
    __syncthreads();
    if(t < 16){
        int c = t>>2, ii = t&3;
        float s = 0.f;
        for(int q=0;q<8;q++) s += rp[c][ii][q];
        g_small[OFF_OR + c*NND + i0 + ii] = s;
    }
    #pragma unroll
    for(int jb=0;jb<8;jb++){
        int j = jb*256 + t;
        atomicAdd(&g_small[OFF_OC + 0*NND + j], colacc[jb][0]);
        atomicAdd(&g_small[OFF_OC + 1*NND + j], colacc[jb][1]);
        atomicAdd(&g_small[OFF_OC + 2*NND + j], colacc[jb][2]);
        atomicAdd(&g_small[OFF_OC + 3*NND + j], colacc[jb][3]);
    }
}

// ---------------- out-layer: x2 = sum_c dsn(eo_c) @ Whout ----------------
__global__ void k_outmm(const float* __restrict__ dout){
    int n0 = blockIdx.x*32;
    int kbase = blockIdx.y*256;
    int t = threadIdx.x;
    __shared__ float asS[32][33];
    __shared__ float woS[32][16];
    __shared__ float uoS[4][32], iloS[4];
    const float* eo = dout + 128;
    if(t < 32){
        #pragma unroll
        for(int c=0;c<4;c++) uoS[c][t] = g_uo[c*NND + n0 + t];
    }
    if(t < 4) iloS[t] = g_ilo[t];
    int bn = t>>3, bm4 = (t&7)*4;
    int na = t>>3, gp = (t&7)*2;
    float acc0 = 0.f, acc1 = 0.f;
    __syncthreads();
    for(int mt=0; mt<8; mt++){
        int m0 = kbase + mt*32;
        ((float*)woS)[t]       = g_Whout[(size_t)m0*16 + t];
        ((float*)woS)[t+256]   = g_Whout[(size_t)m0*16 + t + 256];
        #pragma unroll
        for(int k=0;k<4;k++){
            int m = bm4 + k, mg = m0 + m;
            size_t base = (size_t)(n0+bn)*NND + mg;
            float s = 0.f;
            #pragma unroll
            for(int c=0;c<4;c++){
                float e = eo[(size_t)c*NNE + base];
                float wv = g_wo[c*NND + mg];
                s += e > 0.f ? fmaf(e, iloS[c], uoS[c][bn]*wv) : e;
            }
            asS[bn][m] = s;
        }
        __syncthreads();
        #pragma unroll 8
        for(int m=0;m<32;m++){
            float a = asS[na][m];
            acc0 = fmaf(a, woS[m][gp],   acc0);
            acc1 = fmaf(a, woS[m][gp+1], acc1);
        }
        __syncthreads();
    }
    atomicAdd(&g_small[OFF_X2 + (n0+na)*16 + gp],   acc0);
    atomicAdd(&g_small[OFF_X2 + (n0+na)*16 + gp+1], acc1);
}

// ---------------- bn1 stats ----------------
__global__ void k_bn1stats(){
    int t = threadIdx.x;
    int col = t&15, rg = t>>4;
    float s = 0.f, ss = 0.f;
    for(int r=0;r<128;r++){
        float v = g_small[OFF_X2 + (rg*128 + r)*16 + col];
        s += v; ss += v*v;
    }
    __shared__ float S[16][17], SS[16][17];
    S[rg][col] = s; SS[rg][col] = ss;
    __syncthreads();
    if(t < 16){
        float a = 0.f, b = 0.f;
        for(int q=0;q<16;q++){ a += S[q][t]; b += SS[q][t]; }
        float m = a / (float)NND;
        float var = b / (float)NND - m*m;
        g_mean[t] = m;
        g_rstd[t] = rsqrtf(var + 1e-5f);
    }
}

// ---------------- per-node tail ----------------
__global__ void k_tail1(const float* __restrict__ bn1g, const float* __restrict__ bn1b,
                        const float* __restrict__ bss, const float* __restrict__ bsh,
                        const float* __restrict__ m1w1, const float* __restrict__ m1b1,
                        const float* __restrict__ m1w2, const float* __restrict__ m1b2,
                        const int* __restrict__ gidx, const int* __restrict__ didx){
    int t = threadIdx.x;
    int w = t>>5, l = t&31;
    int n = blockIdx.x*8 + w;
    __shared__ float xsS[8][17], g1S[8][65];
    int di = didx[n];
    if(l < 16){
        float v = g_small[OFF_X2 + n*16 + l];
        float xb = elu1((v - g_mean[l]) * g_rstd[l] * bn1g[l] + bn1b[l]);
        float xs = xb * bss[di*16 + l] + bsh[di*16 + l];
        xsS[w][l] = fmaxf(xs, 0.f);
    }
    __syncwarp();
    float a0 = m1b1[l], a1 = m1b1[l+32];
    #pragma unroll
    for(int k=0;k<16;k++){
        float x = xsS[w][k];
        a0 = fmaf(x, m1w1[k*64 + l],      a0);
        a1 = fmaf(x, m1w1[k*64 + l + 32], a1);
    }
    g1S[w][l]    = fmaxf(a0, 0.f);
    g1S[w][l+32] = fmaxf(a1, 0.f);
    __syncwarp();
    float c0 = m1b2[l], c1 = m1b2[l+32];
    #pragma unroll 8
    for(int k=0;k<64;k++){
        float x = g1S[w][k];
        c0 = fmaf(x, m1w2[k*64 + l],      c0);
        c1 = fmaf(x, m1w2[k*64 + l + 32], c1);
    }
    float ns = c1 * (1.f / (1.f + expf(-c0)));
    atomicAdd(&g_small[OFF_GS + gidx[n]*32 + l], ns);
}

// ---------------- graph-level tail ----------------
__global__ void k_tail2(const float* __restrict__ m2w1, const float* __restrict__ m2b1,
                        const float* __restrict__ m2w2, const float* __restrict__ m2b2,
                        const float* __restrict__ bn2g, const float* __restrict__ bn2b,
                        float* __restrict__ dout){
    int t = threadIdx.x;
    __shared__ float r1S[8][33], r2S[8][17];
    {
        int g = t>>5, j = t&31;
        float v = m2b1[j];
        #pragma unroll
        for(int k=0;k<32;k++)
            v = fmaf(g_small[OFF_GS + g*32 + k], m2w1[k*32 + j], v);
        r1S[g][j] = fmaxf(v, 0.f);
    }
    __syncthreads();
    if(t < 128){
        int g = t>>4, j = t&15;
        float v = m2b2[j];
        #pragma unroll
        for(int k=0;k<32;k++)
            v = fmaf(r1S[g][k], m2w2[k*16 + j], v);
        r2S[g][j] = v;
    }
    __syncthreads();
    if(t < 16){
        float m = 0.f;
        for(int g=0;g<8;g++) m += r2S[g][t];
        m *= 0.125f;
        float var = 0.f;
        for(int g=0;g<8;g++){ float d = r2S[g][t] - m; var += d*d; }
        var *= 0.125f;
        float rs = rsqrtf(var + 1e-5f);
        for(int g=0;g<8;g++)
            dout[g*16 + t] = (r2S[g][t] - m) * rs * bn2g[t] + bn2b[t];
    }
}

// ---------------- launch ----------------
extern "C" void kernel_launch(void* const* d_in, const int* in_sizes, int n_in,
                              void* d_out, int out_size) {
    const float* X      = (const float*)d_in[0];
    const float* ef     = (const float*)d_in[1];
    const float* Wheads = (const float*)d_in[2];
    const float* aheads = (const float*)d_in[3];
    const float* Wout   = (const float*)d_in[4];
    const float* aout   = (const float*)d_in[5];
    const float* bn1g   = (const float*)d_in[6];
    const float* bn1b   = (const float*)d_in[7];
    const float* bss    = (const float*)d_in[8];
    const float* bsh    = (const float*)d_in[9];
    const float* m1w1   = (const float*)d_in[10];
    const float* m1b1   = (const float*)d_in[11];
    const float* m1w2   = (const float*)d_in[12];
    const float* m1b2   = (const float*)d_in[13];
    const float* m2w1   = (const float*)d_in[14];
    const float* m2b1   = (const float*)d_in[15];
    const float* m2w2   = (const float*)d_in[16];
    const float* m2b2   = (const float*)d_in[17];
    const float* bn2g   = (const float*)d_in[18];
    const float* bn2b   = (const float*)d_in[19];
    const int*   gidx   = (const int*)d_in[20];
    const int*   didx   = (const int*)d_in[21];
    float* dout = (float*)d_out;
    (void)in_sizes; (void)n_in; (void)out_size;

    cudaFuncSetAttribute(k_headmm_mma, cudaFuncAttributeMaxDynamicSharedMemorySize, OF_TOT);

    k_zero<<<(SMALL_TOTAL+255)/256, 256>>>();
    k_wh<<<dim3(512,4), 256>>>(X, Wheads, aheads);
    k_whsplit<<<dim3(64,4), 256>>>();
    k_rawA<<<512, 256>>>((const float4*)ef);
    k_params<<<4, 256>>>(0);
    k_headAB<<<512, 256>>>((const float4*)ef);
    k_params<<<16, 256>>>(1);
    k_headmm_mma<<<dim3(64,2), 512, OF_TOT>>>((const float4*)ef);
    k_whout<<<2048, 256>>>(Wout);
    k_s12o<<<8, 256>>>(aout);
    k_outA<<<512, 256>>>((const float4*)ef, dout);
    k_params<<<4, 256>>>(2);
    k_outmm<<<dim3(64,8), 256>>>(dout);
    k_bn1stats<<<1, 256>>>();
    k_tail1<<<256, 256>>>(bn1g, bn1b, bss, bsh, m1w1, m1b1, m1w2, m1b2, gidx, didx);
    k_tail2<<<1, 256>>>(m2w1, m2b1, m2w2, m2b2, bn2g, bn2b, dout);
}